// round 9
// baseline (speedup 1.0000x reference)
#include <cuda_runtime.h>
#include <cuda_bf16.h>
#include <cuda_fp16.h>
#include <math.h>
#include <stdint.h>

#define SEQ   4096
#define DIM   1024
#define NHEAD 16
#define DHEAD 64

// ---------------- scratch (no cudaMalloc allowed) ----------------
__device__ float  g_h   [SEQ*DIM];     // x + pe (fp32, residual)
__device__ float  g_proj[SEQ*DIM];     // final projection out (fp32)
__device__ __half g_hf[SEQ*DIM];       // x + pe (fp16, qkv GEMM input)
__device__ __half g_wf[4][DIM*DIM];    // Wq/Wk/Wv/Wo fp16, TRANSPOSED [N,K]
__device__ __half g_qf[SEQ*DIM], g_kf[SEQ*DIM], g_vf[SEQ*DIM];
__device__ __half g_aof[SEQ*DIM];      // attention out (fp16)

// ---------------- helpers ----------------
__device__ __forceinline__ uint32_t saddr(const void* p) {
    return (uint32_t)__cvta_generic_to_shared(p);
}
__device__ __forceinline__ float ex2f(float x) {
    float y; asm("ex2.approx.f32 %0, %1;" : "=f"(y) : "f"(x)); return y;
}
__device__ __forceinline__ int swzi64(int row, int col) {
    return row * 64 + ((((col >> 3) ^ row) & 7) << 3);
}
__device__ __forceinline__ void ldsm4(uint32_t* r, uint32_t a) {
    asm volatile("ldmatrix.sync.aligned.m8n8.x4.shared.b16 {%0,%1,%2,%3},[%4];"
                 : "=r"(r[0]), "=r"(r[1]), "=r"(r[2]), "=r"(r[3]) : "r"(a));
}
__device__ __forceinline__ void ldsm4t(uint32_t* r, uint32_t a) {
    asm volatile("ldmatrix.sync.aligned.m8n8.x4.trans.shared.b16 {%0,%1,%2,%3},[%4];"
                 : "=r"(r[0]), "=r"(r[1]), "=r"(r[2]), "=r"(r[3]) : "r"(a));
}
__device__ __forceinline__ void mma_hf(float* c, const uint32_t* a,
                                       uint32_t b0, uint32_t b1) {
    asm volatile(
        "mma.sync.aligned.m16n8k16.row.col.f32.f16.f16.f32 "
        "{%0,%1,%2,%3},{%4,%5,%6,%7},{%8,%9},{%0,%1,%2,%3};"
        : "+f"(c[0]), "+f"(c[1]), "+f"(c[2]), "+f"(c[3])
        : "r"(a[0]), "r"(a[1]), "r"(a[2]), "r"(a[3]), "r"(b0), "r"(b1));
}
__device__ __forceinline__ uint32_t packh(float a, float b) {
    __half2 t = __floats2half2_rn(a, b);
    return *reinterpret_cast<uint32_t*>(&t);
}
__device__ __forceinline__ void cpasync16(void* dst, const void* src) {
    asm volatile("cp.async.cg.shared.global [%0], [%1], 16;"
                 :: "r"(saddr(dst)), "l"(src));
}
__device__ __forceinline__ void cp_commit() {
    asm volatile("cp.async.commit_group;" ::: "memory");
}
template <int N> __device__ __forceinline__ void cp_wait() {
    asm volatile("cp.async.wait_group %0;" :: "n"(N) : "memory");
}

// ---------------- h = x + pe (fp32 + fp16) ----------------
__global__ __launch_bounds__(256) void add_pe(const float* __restrict__ x,
                                              float* __restrict__ h,
                                              __half* __restrict__ hf) {
    int row = blockIdx.x;
    int c0  = threadIdx.x * 4;
    const float kf = -9.210340371976184f / (float)DIM;
    float4 xv = *reinterpret_cast<const float4*>(x + (size_t)row * DIM + c0);
    float v[4] = {xv.x, xv.y, xv.z, xv.w};
    float o[4];
#pragma unroll
    for (int e = 0; e < 4; e++) {
        int c = c0 + e;
        float div = expf((float)(c & ~1) * kf);
        float arg = (float)row * div;
        o[e] = v[e] + ((c & 1) ? cosf(arg) : sinf(arg));
    }
    size_t base = (size_t)row * DIM + c0;
    *reinterpret_cast<float4*>(h + base) = make_float4(o[0], o[1], o[2], o[3]);
    *reinterpret_cast<__half2*>(hf + base)     = __floats2half2_rn(o[0], o[1]);
    *reinterpret_cast<__half2*>(hf + base + 2) = __floats2half2_rn(o[2], o[3]);
}

// ---------------- fp16 weight transpose (4 weights): Wt[n,k] = W[k,n] --------
__global__ __launch_bounds__(256) void whalf_t(const float* __restrict__ W0,
                                               const float* __restrict__ W1,
                                               const float* __restrict__ W2,
                                               const float* __restrict__ W3,
                                               __half* __restrict__ outw) {
    __shared__ float t[32][33];
    const float* Ws[4] = {W0, W1, W2, W3};
    const float* W = Ws[blockIdx.z];
    __half* o = outw + (size_t)blockIdx.z * DIM * DIM;
    int k0 = blockIdx.x * 32, n0 = blockIdx.y * 32;
    int tx = threadIdx.x, ty = threadIdx.y;
#pragma unroll
    for (int j = 0; j < 4; j++)
        t[ty + 8 * j][tx] = W[(size_t)(k0 + ty + 8 * j) * DIM + n0 + tx];
    __syncthreads();
#pragma unroll
    for (int j = 0; j < 4; j++)
        o[(size_t)(n0 + ty + 8 * j) * DIM + k0 + tx] =
            __float2half_rn(t[tx][ty + 8 * j]);
}

// ---------------- fused q/k/v GEMM: single fp16 product ----------------
__global__ __launch_bounds__(256, 2) void gemm_qkv(
    const __half* __restrict__ A, const __half* __restrict__ Wf,
    const float* __restrict__ bq, const float* __restrict__ bk,
    const float* __restrict__ bv,
    __half* __restrict__ Qo, __half* __restrict__ Ko, __half* __restrict__ Vo) {
    extern __shared__ __half smq[];
    const int tid  = threadIdx.x;
    const int warp = tid >> 5, lane = tid & 31;
    const int g = lane >> 2, t4 = lane & 3;
    const int lr = lane & 7, sub = lane >> 3;
    const int wm = warp & 3, wn = warp >> 2;
    const int wsel = blockIdx.x >> 3;
    const int n0 = (blockIdx.x & 7) * 128;
    const int m0 = blockIdx.y * 128;
    const __half* B = Wf + (size_t)wsel * DIM * DIM;
    const float* bias = (wsel == 0) ? bq : ((wsel == 1) ? bk : bv);
    __half* C = (wsel == 0) ? Qo : ((wsel == 1) ? Ko : Vo);
    const float osc = (wsel == 0) ? 0.18033688011112042f : 1.0f;  // (1/8)*log2e

    auto load_chunk = [&](int kb, int st) {
        __half* sA = smq + st * 16384;
        __half* sB = sA + 8192;
#pragma unroll
        for (int i = 0; i < 4; i++) {
            int id = tid + i * 256;
            int r = id >> 3, cc = id & 7;
            int sidx = (r * 8 + ((cc ^ r) & 7)) * 8;
            cpasync16(sA + sidx, A + (size_t)(m0 + r) * DIM + kb * 64 + cc * 8);
            cpasync16(sB + sidx, B + (size_t)(n0 + r) * DIM + kb * 64 + cc * 8);
        }
    };

    float acc[2][8][4];
#pragma unroll
    for (int mt = 0; mt < 2; mt++)
#pragma unroll
        for (int nt = 0; nt < 8; nt++)
#pragma unroll
            for (int e = 0; e < 4; e++) acc[mt][nt][e] = 0.f;

    load_chunk(0, 0);
    cp_commit();

    const int NCH = DIM / 64;
    for (int kb = 0; kb < NCH; kb++) {
        int st = kb & 1;
        if (kb + 1 < NCH) { load_chunk(kb + 1, st ^ 1); cp_commit(); cp_wait<1>(); }
        else              { cp_wait<0>(); }
        __syncthreads();
        __half* sA = smq + st * 16384;
        __half* sB = sA + 8192;
#pragma unroll
        for (int kk = 0; kk < 4; kk++) {
            uint32_t af[2][4];
#pragma unroll
            for (int mt = 0; mt < 2; mt++)
                ldsm4(af[mt], saddr(sA + swzi64(wm * 32 + mt * 16 + lr + (sub & 1) * 8,
                                                kk * 16 + (sub >> 1) * 8)));
#pragma unroll
            for (int ntt = 0; ntt < 4; ntt++) {
                uint32_t bfg[4];
                ldsm4(bfg, saddr(sB + swzi64(wn * 64 + ntt * 16 + lr + (sub >> 1) * 8,
                                             kk * 16 + (sub & 1) * 8)));
#pragma unroll
                for (int mt = 0; mt < 2; mt++) {
                    mma_hf(acc[mt][2 * ntt],     af[mt], bfg[0], bfg[1]);
                    mma_hf(acc[mt][2 * ntt + 1], af[mt], bfg[2], bfg[3]);
                }
            }
        }
        __syncthreads();
    }

#pragma unroll
    for (int mt = 0; mt < 2; mt++) {
#pragma unroll
        for (int nt = 0; nt < 8; nt++) {
            int row0 = m0 + wm * 32 + mt * 16 + g;
            int col  = n0 + wn * 64 + nt * 8 + t4 * 2;
            float b0 = bias[col], b1 = bias[col + 1];
            *reinterpret_cast<__half2*>(C + (size_t)row0 * DIM + col) =
                __floats2half2_rn((acc[mt][nt][0] + b0) * osc,
                                  (acc[mt][nt][1] + b1) * osc);
            *reinterpret_cast<__half2*>(C + (size_t)(row0 + 8) * DIM + col) =
                __floats2half2_rn((acc[mt][nt][2] + b0) * osc,
                                  (acc[mt][nt][3] + b1) * osc);
        }
    }
}

// ---------------- out-proj GEMM: single fp16 product, fp32 out ----------------
__global__ __launch_bounds__(256, 2) void gemm_out(
    const __half* __restrict__ A, const __half* __restrict__ B,
    const float* __restrict__ bias, float* __restrict__ Cf) {
    extern __shared__ __half smq[];
    const int tid  = threadIdx.x;
    const int warp = tid >> 5, lane = tid & 31;
    const int g = lane >> 2, t4 = lane & 3;
    const int lr = lane & 7, sub = lane >> 3;
    const int wm = warp & 3, wn = warp >> 2;
    const int m0 = blockIdx.y * 128, n0 = blockIdx.x * 128;

    auto load_chunk = [&](int kb, int st) {
        __half* sA = smq + st * 16384;
        __half* sB = sA + 8192;
#pragma unroll
        for (int i = 0; i < 4; i++) {
            int id = tid + i * 256;
            int r = id >> 3, cc = id & 7;
            int sidx = (r * 8 + ((cc ^ r) & 7)) * 8;
            cpasync16(sA + sidx, A + (size_t)(m0 + r) * DIM + kb * 64 + cc * 8);
            cpasync16(sB + sidx, B + (size_t)(n0 + r) * DIM + kb * 64 + cc * 8);
        }
    };

    float acc[2][8][4];
#pragma unroll
    for (int mt = 0; mt < 2; mt++)
#pragma unroll
        for (int nt = 0; nt < 8; nt++)
#pragma unroll
            for (int e = 0; e < 4; e++) acc[mt][nt][e] = 0.f;

    load_chunk(0, 0);
    cp_commit();

    const int NCH = DIM / 64;
    for (int kb = 0; kb < NCH; kb++) {
        int st = kb & 1;
        if (kb + 1 < NCH) { load_chunk(kb + 1, st ^ 1); cp_commit(); cp_wait<1>(); }
        else              { cp_wait<0>(); }
        __syncthreads();
        __half* sA = smq + st * 16384;
        __half* sB = sA + 8192;
#pragma unroll
        for (int kk = 0; kk < 4; kk++) {
            uint32_t af[2][4];
#pragma unroll
            for (int mt = 0; mt < 2; mt++)
                ldsm4(af[mt], saddr(sA + swzi64(wm * 32 + mt * 16 + lr + (sub & 1) * 8,
                                                kk * 16 + (sub >> 1) * 8)));
#pragma unroll
            for (int ntt = 0; ntt < 4; ntt++) {
                uint32_t bfg[4];
                ldsm4(bfg, saddr(sB + swzi64(wn * 64 + ntt * 16 + lr + (sub >> 1) * 8,
                                             kk * 16 + (sub & 1) * 8)));
#pragma unroll
                for (int mt = 0; mt < 2; mt++) {
                    mma_hf(acc[mt][2 * ntt],     af[mt], bfg[0], bfg[1]);
                    mma_hf(acc[mt][2 * ntt + 1], af[mt], bfg[2], bfg[3]);
                }
            }
        }
        __syncthreads();
    }

#pragma unroll
    for (int mt = 0; mt < 2; mt++) {
#pragma unroll
        for (int nt = 0; nt < 8; nt++) {
            int row0 = m0 + wm * 32 + mt * 16 + g;
            int col  = n0 + wn * 64 + nt * 8 + t4 * 2;
            float b0 = bias[col], b1 = bias[col + 1];
            *reinterpret_cast<float2*>(Cf + (size_t)row0 * DIM + col) =
                make_float2(acc[mt][nt][0] + b0, acc[mt][nt][1] + b1);
            *reinterpret_cast<float2*>(Cf + (size_t)(row0 + 8) * DIM + col) =
                make_float2(acc[mt][nt][2] + b0, acc[mt][nt][3] + b1);
        }
    }
}

// ---------------- flash attention: 3-stage KV ring, one sync/tile, ----------
// ---------------- warp-vote skip-correction -----------------------------
// smem (halfs): Q[0..8191] | K st{0,1,2} @8192+st*4096 | V st{0,1,2} @20480+st*4096
__global__ __launch_bounds__(256, 2) void flash_hf(
    const __half* __restrict__ Qf,
    const __half* __restrict__ Kf,
    const __half* __restrict__ Vf,
    __half* __restrict__ Of) {
    extern __shared__ __half smh[];
    __half* sQ = smh;                    // 128 x 64

    const int tid  = threadIdx.x;
    const int warp = tid >> 5, lane = tid & 31;
    const int g = lane >> 2, t4 = lane & 3;
    const int lr = lane & 7, sub = lane >> 3;
    const int rbase = warp * 16;
    const int head  = blockIdx.y;
    const int qt    = blockIdx.x;

    {
        const __half* qb = Qf + (size_t)(qt * 128) * DIM + head * DHEAD;
#pragma unroll
        for (int i = 0; i < 4; i++) {
            int id = tid + i * 256;
            int r = id >> 3, cc = id & 7;
            cpasync16(sQ + (r * 64 + ((cc ^ r) & 7) * 8),
                      qb + (size_t)r * DIM + cc * 8);
        }
    }
    auto load_kv = [&](int t, int st) {
        __half* sK = smh + 8192  + st * 4096;
        __half* sV = smh + 20480 + st * 4096;
        const size_t base = (size_t)(t * 64) * DIM + head * DHEAD;
#pragma unroll
        for (int i = 0; i < 2; i++) {
            int id = tid + i * 256;
            int r = id >> 3, cc = id & 7;
            int sidx = (r * 8 + ((cc ^ r) & 7)) * 8;
            cpasync16(sK + sidx, Kf + base + (size_t)r * DIM + cc * 8);
            cpasync16(sV + sidx, Vf + base + (size_t)r * DIM + cc * 8);
        }
    };

    float m_i[2], l_i[2], o[8][4];
    m_i[0] = m_i[1] = -1e30f;
    l_i[0] = l_i[1] = 0.f;               // per-thread partial (4 cols each row)
#pragma unroll
    for (int nt = 0; nt < 8; nt++)
#pragma unroll
        for (int e = 0; e < 4; e++) o[nt][e] = 0.f;

    const int NT = SEQ / 64;

    load_kv(0, 0);      // group 0 (also carries Q)
    cp_commit();
    load_kv(1, 1);      // group 1
    cp_commit();

    int st = 0, ld = 2;                  // compute stage, load stage
    for (int t = 0; t < NT; t++) {
        if (t + 1 < NT) cp_wait<1>();    // tile t's group done
        else            cp_wait<0>();
        __syncthreads();                 // bounds warp skew to 1 iter; makes loads visible
        if (t + 2 < NT) { load_kv(t + 2, ld); cp_commit();
                          ld = (ld == 2) ? 0 : ld + 1; }
        __half* sK = smh + 8192  + st * 4096;
        __half* sV = smh + 20480 + st * 4096;
        st = (st == 2) ? 0 : st + 1;

        // ---- S = Q * K^T (q pre-scaled by (1/8)*log2e) ----
        float s[8][4];
#pragma unroll
        for (int nt = 0; nt < 8; nt++)
#pragma unroll
            for (int e = 0; e < 4; e++) s[nt][e] = 0.f;
#pragma unroll
        for (int kk = 0; kk < 4; kk++) {
            uint32_t qf[4];
            ldsm4(qf, saddr(sQ + swzi64(rbase + lr + (sub & 1) * 8,
                                        kk * 16 + (sub >> 1) * 8)));
#pragma unroll
            for (int ntt = 0; ntt < 4; ntt++) {
                uint32_t kf[4];
                ldsm4(kf, saddr(sK + swzi64(ntt * 16 + lr + (sub >> 1) * 8,
                                            kk * 16 + (sub & 1) * 8)));
                mma_hf(s[2 * ntt],     qf, kf[0], kf[1]);
                mma_hf(s[2 * ntt + 1], qf, kf[2], kf[3]);
            }
        }

        // ---- online softmax (log2 domain), warp-vote skip-correction ----
        float mx[2];
#pragma unroll
        for (int r = 0; r < 2; r++) {
            float m = -1e30f;
#pragma unroll
            for (int j = 0; j < 8; j++)
                m = fmaxf(m, fmaxf(s[j][2 * r], s[j][2 * r + 1]));
            m = fmaxf(m, __shfl_xor_sync(0xffffffffu, m, 1));
            m = fmaxf(m, __shfl_xor_sync(0xffffffffu, m, 2));
            mx[r] = m;
        }
        bool up = (mx[0] > m_i[0]) || (mx[1] > m_i[1]);
        if (__any_sync(0xffffffffu, up)) {
#pragma unroll
            for (int r = 0; r < 2; r++) {
                float mnew = fmaxf(m_i[r], mx[r]);
                float corr = ex2f(m_i[r] - mnew);
                m_i[r] = mnew;
                l_i[r] *= corr;
#pragma unroll
                for (int nt = 0; nt < 8; nt++) {
                    o[nt][2 * r]     *= corr;
                    o[nt][2 * r + 1] *= corr;
                }
            }
        }
#pragma unroll
        for (int r = 0; r < 2; r++) {
            float rs = 0.f;
#pragma unroll
            for (int j = 0; j < 8; j++) {
                float p0 = ex2f(s[j][2 * r] - m_i[r]);
                float p1 = ex2f(s[j][2 * r + 1] - m_i[r]);
                s[j][2 * r] = p0; s[j][2 * r + 1] = p1;
                rs += p0 + p1;
            }
            l_i[r] += rs;
        }

        // ---- O += P * V ----
#pragma unroll
        for (int kk = 0; kk < 4; kk++) {
            int j0 = 2 * kk, j1 = j0 + 1;
            uint32_t aH[4];
            aH[0] = packh(s[j0][0], s[j0][1]);
            aH[1] = packh(s[j0][2], s[j0][3]);
            aH[2] = packh(s[j1][0], s[j1][1]);
            aH[3] = packh(s[j1][2], s[j1][3]);
#pragma unroll
            for (int ntt = 0; ntt < 4; ntt++) {
                uint32_t vf[4];
                ldsm4t(vf, saddr(sV + swzi64(kk * 16 + lr + (sub & 1) * 8,
                                             ntt * 16 + (sub >> 1) * 8)));
                mma_hf(o[2 * ntt],     aH, vf[0], vf[1]);
                mma_hf(o[2 * ntt + 1], aH, vf[2], vf[3]);
            }
        }
    }

    // final l reduction across the 4 lanes sharing each row
#pragma unroll
    for (int r = 0; r < 2; r++) {
        l_i[r] += __shfl_xor_sync(0xffffffffu, l_i[r], 1);
        l_i[r] += __shfl_xor_sync(0xffffffffu, l_i[r], 2);
    }
    float inv0 = 1.f / l_i[0], inv1 = 1.f / l_i[1];
#pragma unroll
    for (int nt = 0; nt < 8; nt++) {
        int row0 = qt * 128 + rbase + g;
        int col  = head * DHEAD + nt * 8 + t4 * 2;
        *reinterpret_cast<__half2*>(Of + (size_t)row0 * DIM + col) =
            __floats2half2_rn(o[nt][0] * inv0, o[nt][1] * inv0);
        *reinterpret_cast<__half2*>(Of + (size_t)(row0 + 8) * DIM + col) =
            __floats2half2_rn(o[nt][2] * inv1, o[nt][3] * inv1);
    }
}

// ---------------- residual + layernorm ----------------
__global__ __launch_bounds__(256) void ln_kernel(const float* __restrict__ h,
                                                 const float* __restrict__ pr,
                                                 const float* __restrict__ gamma,
                                                 const float* __restrict__ beta,
                                                 float* __restrict__ out) {
    __shared__ float red[16];
    __shared__ float s_mu, s_rstd;
    int row = blockIdx.x, tid = threadIdx.x;
    int c0 = tid * 4;
    float4 hv = *reinterpret_cast<const float4*>(h  + (size_t)row * DIM + c0);
    float4 pv = *reinterpret_cast<const float4*>(pr + (size_t)row * DIM + c0);
    float y[4] = {hv.x + pv.x, hv.y + pv.y, hv.z + pv.z, hv.w + pv.w};
    float sum = y[0] + y[1] + y[2] + y[3];
    float sq  = y[0]*y[0] + y[1]*y[1] + y[2]*y[2] + y[3]*y[3];
#pragma unroll
    for (int off = 16; off; off >>= 1) {
        sum += __shfl_xor_sync(0xffffffffu, sum, off);
        sq  += __shfl_xor_sync(0xffffffffu, sq,  off);
    }
    int w = tid >> 5;
    if ((tid & 31) == 0) { red[w] = sum; red[8 + w] = sq; }
    __syncthreads();
    if (tid == 0) {
        float ts = 0.f, tq = 0.f;
        for (int i = 0; i < 8; i++) { ts += red[i]; tq += red[8 + i]; }
        float mu = ts / (float)DIM;
        s_mu   = mu;
        s_rstd = rsqrtf(tq / (float)DIM - mu * mu + 1e-5f);
    }
    __syncthreads();
    float4 gv = *reinterpret_cast<const float4*>(gamma + c0);
    float4 bv = *reinterpret_cast<const float4*>(beta  + c0);
    float mu = s_mu, rs = s_rstd;
    float4 ov;
    ov.x = (y[0] - mu) * rs * gv.x + bv.x;
    ov.y = (y[1] - mu) * rs * gv.y + bv.y;
    ov.z = (y[2] - mu) * rs * gv.z + bv.z;
    ov.w = (y[3] - mu) * rs * gv.w + bv.w;
    *reinterpret_cast<float4*>(out + (size_t)row * DIM + c0) = ov;
}

// ---------------------------------------------------------------------------
extern "C" void kernel_launch(void* const* d_in, const int* in_sizes, int n_in,
                              void* d_out, int out_size) {
    (void)in_sizes; (void)n_in; (void)out_size;
    const float* x     = (const float*)d_in[0];
    const float* Wq    = (const float*)d_in[1];
    const float* bq    = (const float*)d_in[2];
    const float* Wk    = (const float*)d_in[3];
    const float* bk    = (const float*)d_in[4];
    const float* Wv    = (const float*)d_in[5];
    const float* bv    = (const float*)d_in[6];
    const float* Wo    = (const float*)d_in[7];
    const float* bo    = (const float*)d_in[8];
    const float* gamma = (const float*)d_in[9];
    const float* beta  = (const float*)d_in[10];
    float* out = (float*)d_out;

    void* p;
    cudaGetSymbolAddress(&p, g_h);    float* h    = (float*)p;
    cudaGetSymbolAddress(&p, g_proj); float* proj = (float*)p;
    cudaGetSymbolAddress(&p, g_hf);   __half* hf = (__half*)p;
    cudaGetSymbolAddress(&p, g_wf);   __half* wf = (__half*)p;
    cudaGetSymbolAddress(&p, g_qf);   __half* qf = (__half*)p;
    cudaGetSymbolAddress(&p, g_kf);   __half* kf = (__half*)p;
    cudaGetSymbolAddress(&p, g_vf);   __half* vf = (__half*)p;
    cudaGetSymbolAddress(&p, g_aof);  __half* aof = (__half*)p;

    const int SMEM_G = 65536;            // 2 stages x 32KB
    const int SMEM_F = 65536;            // Q 16KB + 3 stages x (8+8)KB
    cudaFuncSetAttribute(gemm_qkv,
                         cudaFuncAttributeMaxDynamicSharedMemorySize, SMEM_G);
    cudaFuncSetAttribute(gemm_out,
                         cudaFuncAttributeMaxDynamicSharedMemorySize, SMEM_G);
    cudaFuncSetAttribute(flash_hf,
                         cudaFuncAttributeMaxDynamicSharedMemorySize, SMEM_F);

    add_pe<<<SEQ, 256>>>(x, h, hf);
    whalf_t<<<dim3(DIM / 32, DIM / 32, 4), dim3(32, 8)>>>(Wq, Wk, Wv, Wo, wf);

    gemm_qkv<<<dim3(24, SEQ / 128), 256, SMEM_G>>>(hf, wf, bq, bk, bv,
                                                   qf, kf, vf);

    flash_hf<<<dim3(SEQ / 128, NHEAD), 256, SMEM_F>>>(qf, kf, vf, aof);

    gemm_out<<<dim3(DIM / 128, SEQ / 128), 256, SMEM_G>>>(
        aof, wf + 3 * (size_t)DIM * DIM, bo, proj);

    ln_kernel<<<SEQ, 256>>>(h, proj, gamma, beta, out);
}

// round 10
// speedup vs baseline: 1.0376x; 1.0376x over previous
#include <cuda_runtime.h>
#include <cuda_bf16.h>
#include <cuda_fp16.h>
#include <math.h>
#include <stdint.h>

#define SEQ   4096
#define DIM   1024
#define NHEAD 16
#define DHEAD 64

// ---------------- scratch (no cudaMalloc allowed) ----------------
__device__ float  g_h   [SEQ*DIM];     // x + pe (fp32, residual)
__device__ float  g_proj[SEQ*DIM];     // final projection out (fp32)
__device__ __half g_hf[SEQ*DIM];       // x + pe (fp16, qkv GEMM input)
__device__ __half g_wf[4][DIM*DIM];    // Wq/Wk/Wv/Wo fp16, TRANSPOSED [N,K]
__device__ __half g_qf[SEQ*DIM], g_kf[SEQ*DIM], g_vf[SEQ*DIM];
__device__ __half g_aof[SEQ*DIM];      // attention out (fp16)

// ---------------- helpers ----------------
__device__ __forceinline__ uint32_t saddr(const void* p) {
    return (uint32_t)__cvta_generic_to_shared(p);
}
__device__ __forceinline__ float ex2f(float x) {
    float y; asm("ex2.approx.f32 %0, %1;" : "=f"(y) : "f"(x)); return y;
}
__device__ __forceinline__ uint32_t ex2h2(uint32_t x) {
    uint32_t y; asm("ex2.approx.f16x2 %0, %1;" : "=r"(y) : "r"(x)); return y;
}
__device__ __forceinline__ int swzi64(int row, int col) {
    return row * 64 + ((((col >> 3) ^ row) & 7) << 3);
}
__device__ __forceinline__ void ldsm4(uint32_t* r, uint32_t a) {
    asm volatile("ldmatrix.sync.aligned.m8n8.x4.shared.b16 {%0,%1,%2,%3},[%4];"
                 : "=r"(r[0]), "=r"(r[1]), "=r"(r[2]), "=r"(r[3]) : "r"(a));
}
__device__ __forceinline__ void ldsm4t(uint32_t* r, uint32_t a) {
    asm volatile("ldmatrix.sync.aligned.m8n8.x4.trans.shared.b16 {%0,%1,%2,%3},[%4];"
                 : "=r"(r[0]), "=r"(r[1]), "=r"(r[2]), "=r"(r[3]) : "r"(a));
}
__device__ __forceinline__ void mma_hf(float* c, const uint32_t* a,
                                       uint32_t b0, uint32_t b1) {
    asm volatile(
        "mma.sync.aligned.m16n8k16.row.col.f32.f16.f16.f32 "
        "{%0,%1,%2,%3},{%4,%5,%6,%7},{%8,%9},{%0,%1,%2,%3};"
        : "+f"(c[0]), "+f"(c[1]), "+f"(c[2]), "+f"(c[3])
        : "r"(a[0]), "r"(a[1]), "r"(a[2]), "r"(a[3]), "r"(b0), "r"(b1));
}
__device__ __forceinline__ uint32_t pack2h(float a, float b) {
    __half2 t = __floats2half2_rn(a, b);
    return *reinterpret_cast<uint32_t*>(&t);
}
__device__ __forceinline__ void cpasync16(void* dst, const void* src) {
    asm volatile("cp.async.cg.shared.global [%0], [%1], 16;"
                 :: "r"(saddr(dst)), "l"(src));
}
__device__ __forceinline__ void cp_commit() {
    asm volatile("cp.async.commit_group;" ::: "memory");
}
template <int N> __device__ __forceinline__ void cp_wait() {
    asm volatile("cp.async.wait_group %0;" :: "n"(N) : "memory");
}

// ---------------- h = x + pe (fp32 + fp16) ----------------
__global__ __launch_bounds__(256) void add_pe(const float* __restrict__ x,
                                              float* __restrict__ h,
                                              __half* __restrict__ hf) {
    int row = blockIdx.x;
    int c0  = threadIdx.x * 4;
    const float kf = -9.210340371976184f / (float)DIM;
    float4 xv = *reinterpret_cast<const float4*>(x + (size_t)row * DIM + c0);
    float v[4] = {xv.x, xv.y, xv.z, xv.w};
    float o[4];
#pragma unroll
    for (int e = 0; e < 4; e++) {
        int c = c0 + e;
        float div = expf((float)(c & ~1) * kf);
        float arg = (float)row * div;
        o[e] = v[e] + ((c & 1) ? cosf(arg) : sinf(arg));
    }
    size_t base = (size_t)row * DIM + c0;
    *reinterpret_cast<float4*>(h + base) = make_float4(o[0], o[1], o[2], o[3]);
    *reinterpret_cast<__half2*>(hf + base)     = __floats2half2_rn(o[0], o[1]);
    *reinterpret_cast<__half2*>(hf + base + 2) = __floats2half2_rn(o[2], o[3]);
}

// ---------------- fp16 weight transpose (4 weights): Wt[n,k] = W[k,n] --------
__global__ __launch_bounds__(256) void whalf_t(const float* __restrict__ W0,
                                               const float* __restrict__ W1,
                                               const float* __restrict__ W2,
                                               const float* __restrict__ W3,
                                               __half* __restrict__ outw) {
    __shared__ float t[32][33];
    const float* Ws[4] = {W0, W1, W2, W3};
    const float* W = Ws[blockIdx.z];
    __half* o = outw + (size_t)blockIdx.z * DIM * DIM;
    int k0 = blockIdx.x * 32, n0 = blockIdx.y * 32;
    int tx = threadIdx.x, ty = threadIdx.y;
#pragma unroll
    for (int j = 0; j < 4; j++)
        t[ty + 8 * j][tx] = W[(size_t)(k0 + ty + 8 * j) * DIM + n0 + tx];
    __syncthreads();
#pragma unroll
    for (int j = 0; j < 4; j++)
        o[(size_t)(n0 + ty + 8 * j) * DIM + k0 + tx] =
            __float2half_rn(t[tx][ty + 8 * j]);
}

// ---------------- fused q/k/v GEMM: single fp16 product ----------------
__global__ __launch_bounds__(256, 2) void gemm_qkv(
    const __half* __restrict__ A, const __half* __restrict__ Wf,
    const float* __restrict__ bq, const float* __restrict__ bk,
    const float* __restrict__ bv,
    __half* __restrict__ Qo, __half* __restrict__ Ko, __half* __restrict__ Vo) {
    extern __shared__ __half smq[];
    const int tid  = threadIdx.x;
    const int warp = tid >> 5, lane = tid & 31;
    const int g = lane >> 2, t4 = lane & 3;
    const int lr = lane & 7, sub = lane >> 3;
    const int wm = warp & 3, wn = warp >> 2;
    const int wsel = blockIdx.x >> 3;
    const int n0 = (blockIdx.x & 7) * 128;
    const int m0 = blockIdx.y * 128;
    const __half* B = Wf + (size_t)wsel * DIM * DIM;
    const float* bias = (wsel == 0) ? bq : ((wsel == 1) ? bk : bv);
    __half* C = (wsel == 0) ? Qo : ((wsel == 1) ? Ko : Vo);
    const float osc = (wsel == 0) ? 0.18033688011112042f : 1.0f;  // (1/8)*log2e

    auto load_chunk = [&](int kb, int st) {
        __half* sA = smq + st * 16384;
        __half* sB = sA + 8192;
#pragma unroll
        for (int i = 0; i < 4; i++) {
            int id = tid + i * 256;
            int r = id >> 3, cc = id & 7;
            int sidx = (r * 8 + ((cc ^ r) & 7)) * 8;
            cpasync16(sA + sidx, A + (size_t)(m0 + r) * DIM + kb * 64 + cc * 8);
            cpasync16(sB + sidx, B + (size_t)(n0 + r) * DIM + kb * 64 + cc * 8);
        }
    };

    float acc[2][8][4];
#pragma unroll
    for (int mt = 0; mt < 2; mt++)
#pragma unroll
        for (int nt = 0; nt < 8; nt++)
#pragma unroll
            for (int e = 0; e < 4; e++) acc[mt][nt][e] = 0.f;

    load_chunk(0, 0);
    cp_commit();

    const int NCH = DIM / 64;
    for (int kb = 0; kb < NCH; kb++) {
        int st = kb & 1;
        if (kb + 1 < NCH) { load_chunk(kb + 1, st ^ 1); cp_commit(); cp_wait<1>(); }
        else              { cp_wait<0>(); }
        __syncthreads();
        __half* sA = smq + st * 16384;
        __half* sB = sA + 8192;
#pragma unroll
        for (int kk = 0; kk < 4; kk++) {
            uint32_t af[2][4];
#pragma unroll
            for (int mt = 0; mt < 2; mt++)
                ldsm4(af[mt], saddr(sA + swzi64(wm * 32 + mt * 16 + lr + (sub & 1) * 8,
                                                kk * 16 + (sub >> 1) * 8)));
#pragma unroll
            for (int ntt = 0; ntt < 4; ntt++) {
                uint32_t bfg[4];
                ldsm4(bfg, saddr(sB + swzi64(wn * 64 + ntt * 16 + lr + (sub >> 1) * 8,
                                             kk * 16 + (sub & 1) * 8)));
#pragma unroll
                for (int mt = 0; mt < 2; mt++) {
                    mma_hf(acc[mt][2 * ntt],     af[mt], bfg[0], bfg[1]);
                    mma_hf(acc[mt][2 * ntt + 1], af[mt], bfg[2], bfg[3]);
                }
            }
        }
        __syncthreads();
    }

#pragma unroll
    for (int mt = 0; mt < 2; mt++) {
#pragma unroll
        for (int nt = 0; nt < 8; nt++) {
            int row0 = m0 + wm * 32 + mt * 16 + g;
            int col  = n0 + wn * 64 + nt * 8 + t4 * 2;
            float b0 = bias[col], b1 = bias[col + 1];
            *reinterpret_cast<__half2*>(C + (size_t)row0 * DIM + col) =
                __floats2half2_rn((acc[mt][nt][0] + b0) * osc,
                                  (acc[mt][nt][1] + b1) * osc);
            *reinterpret_cast<__half2*>(C + (size_t)(row0 + 8) * DIM + col) =
                __floats2half2_rn((acc[mt][nt][2] + b0) * osc,
                                  (acc[mt][nt][3] + b1) * osc);
        }
    }
}

// ---------------- out-proj GEMM: single fp16 product, fp32 out ----------------
__global__ __launch_bounds__(256, 2) void gemm_out(
    const __half* __restrict__ A, const __half* __restrict__ B,
    const float* __restrict__ bias, float* __restrict__ Cf) {
    extern __shared__ __half smq[];
    const int tid  = threadIdx.x;
    const int warp = tid >> 5, lane = tid & 31;
    const int g = lane >> 2, t4 = lane & 3;
    const int lr = lane & 7, sub = lane >> 3;
    const int wm = warp & 3, wn = warp >> 2;
    const int m0 = blockIdx.y * 128, n0 = blockIdx.x * 128;

    auto load_chunk = [&](int kb, int st) {
        __half* sA = smq + st * 16384;
        __half* sB = sA + 8192;
#pragma unroll
        for (int i = 0; i < 4; i++) {
            int id = tid + i * 256;
            int r = id >> 3, cc = id & 7;
            int sidx = (r * 8 + ((cc ^ r) & 7)) * 8;
            cpasync16(sA + sidx, A + (size_t)(m0 + r) * DIM + kb * 64 + cc * 8);
            cpasync16(sB + sidx, B + (size_t)(n0 + r) * DIM + kb * 64 + cc * 8);
        }
    };

    float acc[2][8][4];
#pragma unroll
    for (int mt = 0; mt < 2; mt++)
#pragma unroll
        for (int nt = 0; nt < 8; nt++)
#pragma unroll
            for (int e = 0; e < 4; e++) acc[mt][nt][e] = 0.f;

    load_chunk(0, 0);
    cp_commit();

    const int NCH = DIM / 64;
    for (int kb = 0; kb < NCH; kb++) {
        int st = kb & 1;
        if (kb + 1 < NCH) { load_chunk(kb + 1, st ^ 1); cp_commit(); cp_wait<1>(); }
        else              { cp_wait<0>(); }
        __syncthreads();
        __half* sA = smq + st * 16384;
        __half* sB = sA + 8192;
#pragma unroll
        for (int kk = 0; kk < 4; kk++) {
            uint32_t af[2][4];
#pragma unroll
            for (int mt = 0; mt < 2; mt++)
                ldsm4(af[mt], saddr(sA + swzi64(wm * 32 + mt * 16 + lr + (sub & 1) * 8,
                                                kk * 16 + (sub >> 1) * 8)));
#pragma unroll
            for (int ntt = 0; ntt < 4; ntt++) {
                uint32_t bfg[4];
                ldsm4(bfg, saddr(sB + swzi64(wn * 64 + ntt * 16 + lr + (sub >> 1) * 8,
                                             kk * 16 + (sub & 1) * 8)));
#pragma unroll
                for (int mt = 0; mt < 2; mt++) {
                    mma_hf(acc[mt][2 * ntt],     af[mt], bfg[0], bfg[1]);
                    mma_hf(acc[mt][2 * ntt + 1], af[mt], bfg[2], bfg[3]);
                }
            }
        }
        __syncthreads();
    }

#pragma unroll
    for (int mt = 0; mt < 2; mt++) {
#pragma unroll
        for (int nt = 0; nt < 8; nt++) {
            int row0 = m0 + wm * 32 + mt * 16 + g;
            int col  = n0 + wn * 64 + nt * 8 + t4 * 2;
            float b0 = bias[col], b1 = bias[col + 1];
            *reinterpret_cast<float2*>(Cf + (size_t)row0 * DIM + col) =
                make_float2(acc[mt][nt][0] + b0, acc[mt][nt][1] + b1);
            *reinterpret_cast<float2*>(Cf + (size_t)(row0 + 8) * DIM + col) =
                make_float2(acc[mt][nt][2] + b0, acc[mt][nt][3] + b1);
        }
    }
}

// ---------------- flash attention: R8 structure + f16x2 softmax --------------
// smem (halfs): Q[0..8191] | K st{0,1} @8192+st*4096 | V st{0,1} @16384+st*4096
__global__ __launch_bounds__(256, 2) void flash_hf(
    const __half* __restrict__ Qf,
    const __half* __restrict__ Kf,
    const __half* __restrict__ Vf,
    __half* __restrict__ Of) {
    extern __shared__ __half smh[];
    __half* sQ = smh;                    // 128 x 64

    const int tid  = threadIdx.x;
    const int warp = tid >> 5, lane = tid & 31;
    const int g = lane >> 2, t4 = lane & 3;
    const int lr = lane & 7, sub = lane >> 3;
    const int rbase = warp * 16;
    const int head  = blockIdx.y;
    const int qt    = blockIdx.x;

    {
        const __half* qb = Qf + (size_t)(qt * 128) * DIM + head * DHEAD;
#pragma unroll
        for (int i = 0; i < 4; i++) {
            int id = tid + i * 256;
            int r = id >> 3, cc = id & 7;
            cpasync16(sQ + (r * 64 + ((cc ^ r) & 7) * 8),
                      qb + (size_t)r * DIM + cc * 8);
        }
    }
    auto load_kv = [&](int t, int st) {
        __half* sK = smh + 8192  + st * 4096;
        __half* sV = smh + 16384 + st * 4096;
        const size_t base = (size_t)(t * 64) * DIM + head * DHEAD;
#pragma unroll
        for (int i = 0; i < 2; i++) {
            int id = tid + i * 256;
            int r = id >> 3, cc = id & 7;
            int sidx = (r * 8 + ((cc ^ r) & 7)) * 8;
            cpasync16(sK + sidx, Kf + base + (size_t)r * DIM + cc * 8);
            cpasync16(sV + sidx, Vf + base + (size_t)r * DIM + cc * 8);
        }
    };

    float m_i[2], l_i[2], o[8][4];
    m_i[0] = m_i[1] = -1e30f;
    l_i[0] = l_i[1] = 0.f;               // per-thread partial (4 cols each row)
#pragma unroll
    for (int nt = 0; nt < 8; nt++)
#pragma unroll
        for (int e = 0; e < 4; e++) o[nt][e] = 0.f;

    const int NT = SEQ / 64;

    load_kv(0, 0);
    cp_commit();

    for (int t = 0; t < NT; t++) {
        int st = t & 1;
        if (t + 1 < NT) { load_kv(t + 1, st ^ 1); cp_commit(); cp_wait<1>(); }
        else            { cp_wait<0>(); }
        __syncthreads();
        __half* sK = smh + 8192  + st * 4096;
        __half* sV = smh + 16384 + st * 4096;

        // ---- S = Q * K^T (q pre-scaled by (1/8)*log2e) ----
        float s[8][4];
#pragma unroll
        for (int nt = 0; nt < 8; nt++)
#pragma unroll
            for (int e = 0; e < 4; e++) s[nt][e] = 0.f;
#pragma unroll
        for (int kk = 0; kk < 4; kk++) {
            uint32_t qf[4];
            ldsm4(qf, saddr(sQ + swzi64(rbase + lr + (sub & 1) * 8,
                                        kk * 16 + (sub >> 1) * 8)));
#pragma unroll
            for (int ntt = 0; ntt < 4; ntt++) {
                uint32_t kf[4];
                ldsm4(kf, saddr(sK + swzi64(ntt * 16 + lr + (sub >> 1) * 8,
                                            kk * 16 + (sub & 1) * 8)));
                mma_hf(s[2 * ntt],     qf, kf[0], kf[1]);
                mma_hf(s[2 * ntt + 1], qf, kf[2], kf[3]);
            }
        }

        // ---- online softmax (log2 domain); P computed in f16x2 ----
#pragma unroll
        for (int r = 0; r < 2; r++) {
            float mx = -1e30f;
#pragma unroll
            for (int j = 0; j < 8; j++)
                mx = fmaxf(mx, fmaxf(s[j][2 * r], s[j][2 * r + 1]));
            mx = fmaxf(mx, __shfl_xor_sync(0xffffffffu, mx, 1));
            mx = fmaxf(mx, __shfl_xor_sync(0xffffffffu, mx, 2));
            float mnew = fmaxf(m_i[r], mx);
            float corr = ex2f(m_i[r] - mnew);
            m_i[r] = mnew;
            l_i[r] *= corr;
#pragma unroll
            for (int nt = 0; nt < 8; nt++) {
                o[nt][2 * r]     *= corr;
                o[nt][2 * r + 1] *= corr;
            }
        }
        uint32_t pa[8][2];
        __half2 ll0 = __floats2half2_rn(0.f, 0.f);
        __half2 ll1 = ll0;
#pragma unroll
        for (int j = 0; j < 8; j++) {
            pa[j][0] = ex2h2(pack2h(s[j][0] - m_i[0], s[j][1] - m_i[0]));
            pa[j][1] = ex2h2(pack2h(s[j][2] - m_i[1], s[j][3] - m_i[1]));
            ll0 = __hadd2(ll0, *reinterpret_cast<__half2*>(&pa[j][0]));
            ll1 = __hadd2(ll1, *reinterpret_cast<__half2*>(&pa[j][1]));
        }
        l_i[0] += __low2float(ll0) + __high2float(ll0);
        l_i[1] += __low2float(ll1) + __high2float(ll1);

        // ---- O += P * V ----
#pragma unroll
        for (int kk = 0; kk < 4; kk++) {
            int j0 = 2 * kk, j1 = j0 + 1;
            uint32_t aH[4] = {pa[j0][0], pa[j0][1], pa[j1][0], pa[j1][1]};
#pragma unroll
            for (int ntt = 0; ntt < 4; ntt++) {
                uint32_t vf[4];
                ldsm4t(vf, saddr(sV + swzi64(kk * 16 + lr + (sub & 1) * 8,
                                             ntt * 16 + (sub >> 1) * 8)));
                mma_hf(o[2 * ntt],     aH, vf[0], vf[1]);
                mma_hf(o[2 * ntt + 1], aH, vf[2], vf[3]);
            }
        }
        __syncthreads();
    }

    // final l reduction across the 4 lanes sharing each row
#pragma unroll
    for (int r = 0; r < 2; r++) {
        l_i[r] += __shfl_xor_sync(0xffffffffu, l_i[r], 1);
        l_i[r] += __shfl_xor_sync(0xffffffffu, l_i[r], 2);
    }
    float inv0 = 1.f / l_i[0], inv1 = 1.f / l_i[1];
#pragma unroll
    for (int nt = 0; nt < 8; nt++) {
        int row0 = qt * 128 + rbase + g;
        int col  = head * DHEAD + nt * 8 + t4 * 2;
        *reinterpret_cast<__half2*>(Of + (size_t)row0 * DIM + col) =
            __floats2half2_rn(o[nt][0] * inv0, o[nt][1] * inv0);
        *reinterpret_cast<__half2*>(Of + (size_t)(row0 + 8) * DIM + col) =
            __floats2half2_rn(o[nt][2] * inv1, o[nt][3] * inv1);
    }
}

// ---------------- residual + layernorm ----------------
__global__ __launch_bounds__(256) void ln_kernel(const float* __restrict__ h,
                                                 const float* __restrict__ pr,
                                                 const float* __restrict__ gamma,
                                                 const float* __restrict__ beta,
                                                 float* __restrict__ out) {
    __shared__ float red[16];
    __shared__ float s_mu, s_rstd;
    int row = blockIdx.x, tid = threadIdx.x;
    int c0 = tid * 4;
    float4 hv = *reinterpret_cast<const float4*>(h  + (size_t)row * DIM + c0);
    float4 pv = *reinterpret_cast<const float4*>(pr + (size_t)row * DIM + c0);
    float y[4] = {hv.x + pv.x, hv.y + pv.y, hv.z + pv.z, hv.w + pv.w};
    float sum = y[0] + y[1] + y[2] + y[3];
    float sq  = y[0]*y[0] + y[1]*y[1] + y[2]*y[2] + y[3]*y[3];
#pragma unroll
    for (int off = 16; off; off >>= 1) {
        sum += __shfl_xor_sync(0xffffffffu, sum, off);
        sq  += __shfl_xor_sync(0xffffffffu, sq,  off);
    }
    int w = tid >> 5;
    if ((tid & 31) == 0) { red[w] = sum; red[8 + w] = sq; }
    __syncthreads();
    if (tid == 0) {
        float ts = 0.f, tq = 0.f;
        for (int i = 0; i < 8; i++) { ts += red[i]; tq += red[8 + i]; }
        float mu = ts / (float)DIM;
        s_mu   = mu;
        s_rstd = rsqrtf(tq / (float)DIM - mu * mu + 1e-5f);
    }
    __syncthreads();
    float4 gv = *reinterpret_cast<const float4*>(gamma + c0);
    float4 bv = *reinterpret_cast<const float4*>(beta  + c0);
    float mu = s_mu, rs = s_rstd;
    float4 ov;
    ov.x = (y[0] - mu) * rs * gv.x + bv.x;
    ov.y = (y[1] - mu) * rs * gv.y + bv.y;
    ov.z = (y[2] - mu) * rs * gv.z + bv.z;
    ov.w = (y[3] - mu) * rs * gv.w + bv.w;
    *reinterpret_cast<float4*>(out + (size_t)row * DIM + c0) = ov;
}

// ---------------------------------------------------------------------------
extern "C" void kernel_launch(void* const* d_in, const int* in_sizes, int n_in,
                              void* d_out, int out_size) {
    (void)in_sizes; (void)n_in; (void)out_size;
    const float* x     = (const float*)d_in[0];
    const float* Wq    = (const float*)d_in[1];
    const float* bq    = (const float*)d_in[2];
    const float* Wk    = (const float*)d_in[3];
    const float* bk    = (const float*)d_in[4];
    const float* Wv    = (const float*)d_in[5];
    const float* bv    = (const float*)d_in[6];
    const float* Wo    = (const float*)d_in[7];
    const float* bo    = (const float*)d_in[8];
    const float* gamma = (const float*)d_in[9];
    const float* beta  = (const float*)d_in[10];
    float* out = (float*)d_out;

    void* p;
    cudaGetSymbolAddress(&p, g_h);    float* h    = (float*)p;
    cudaGetSymbolAddress(&p, g_proj); float* proj = (float*)p;
    cudaGetSymbolAddress(&p, g_hf);   __half* hf = (__half*)p;
    cudaGetSymbolAddress(&p, g_wf);   __half* wf = (__half*)p;
    cudaGetSymbolAddress(&p, g_qf);   __half* qf = (__half*)p;
    cudaGetSymbolAddress(&p, g_kf);   __half* kf = (__half*)p;
    cudaGetSymbolAddress(&p, g_vf);   __half* vf = (__half*)p;
    cudaGetSymbolAddress(&p, g_aof);  __half* aof = (__half*)p;

    const int SMEM_G = 65536;            // 2 stages x 32KB
    const int SMEM_F = 49152;            // Q 16KB + (K+V) x 2 stages x 8KB
    cudaFuncSetAttribute(gemm_qkv,
                         cudaFuncAttributeMaxDynamicSharedMemorySize, SMEM_G);
    cudaFuncSetAttribute(gemm_out,
                         cudaFuncAttributeMaxDynamicSharedMemorySize, SMEM_G);
    cudaFuncSetAttribute(flash_hf,
                         cudaFuncAttributeMaxDynamicSharedMemorySize, SMEM_F);

    add_pe<<<SEQ, 256>>>(x, h, hf);
    whalf_t<<<dim3(DIM / 32, DIM / 32, 4), dim3(32, 8)>>>(Wq, Wk, Wv, Wo, wf);

    gemm_qkv<<<dim3(24, SEQ / 128), 256, SMEM_G>>>(hf, wf, bq, bk, bv,
                                                   qf, kf, vf);

    flash_hf<<<dim3(SEQ / 128, NHEAD), 256, SMEM_F>>>(qf, kf, vf, aof);

    gemm_out<<<dim3(DIM / 128, SEQ / 128), 256, SMEM_G>>>(
        aof, wf + 3 * (size_t)DIM * DIM, bo, proj);

    ln_kernel<<<SEQ, 256>>>(h, proj, gamma, beta, out);
}

// round 11
// speedup vs baseline: 1.0546x; 1.0164x over previous
#include <cuda_runtime.h>
#include <cuda_bf16.h>
#include <cuda_fp16.h>
#include <math.h>
#include <stdint.h>

#define SEQ   4096
#define DIM   1024
#define NHEAD 16
#define DHEAD 64

// ---------------- scratch (no cudaMalloc allowed) ----------------
__device__ float  g_h   [SEQ*DIM];     // x + pe (fp32, residual)
__device__ float  g_proj[SEQ*DIM];     // final projection out (fp32)
__device__ __half g_hf[SEQ*DIM];       // x + pe (fp16, qkv GEMM input)
__device__ __half g_wf[4][DIM*DIM];    // Wq/Wk/Wv/Wo fp16, TRANSPOSED [N,K]
__device__ __half g_qf[SEQ*DIM], g_kf[SEQ*DIM], g_vf[SEQ*DIM];
__device__ __half g_aof[SEQ*DIM];      // attention out (fp16)

// ---------------- helpers ----------------
__device__ __forceinline__ uint32_t saddr(const void* p) {
    return (uint32_t)__cvta_generic_to_shared(p);
}
__device__ __forceinline__ float ex2f(float x) {
    float y; asm("ex2.approx.f32 %0, %1;" : "=f"(y) : "f"(x)); return y;
}
__device__ __forceinline__ uint32_t ex2h2(uint32_t x) {
    uint32_t y; asm("ex2.approx.f16x2 %0, %1;" : "=r"(y) : "r"(x)); return y;
}
__device__ __forceinline__ int swzi64(int row, int col) {
    return row * 64 + ((((col >> 3) ^ row) & 7) << 3);
}
__device__ __forceinline__ void ldsm4(uint32_t* r, uint32_t a) {
    asm volatile("ldmatrix.sync.aligned.m8n8.x4.shared.b16 {%0,%1,%2,%3},[%4];"
                 : "=r"(r[0]), "=r"(r[1]), "=r"(r[2]), "=r"(r[3]) : "r"(a));
}
__device__ __forceinline__ void ldsm4t(uint32_t* r, uint32_t a) {
    asm volatile("ldmatrix.sync.aligned.m8n8.x4.trans.shared.b16 {%0,%1,%2,%3},[%4];"
                 : "=r"(r[0]), "=r"(r[1]), "=r"(r[2]), "=r"(r[3]) : "r"(a));
}
__device__ __forceinline__ void mma_hf(float* c, const uint32_t* a,
                                       uint32_t b0, uint32_t b1) {
    asm volatile(
        "mma.sync.aligned.m16n8k16.row.col.f32.f16.f16.f32 "
        "{%0,%1,%2,%3},{%4,%5,%6,%7},{%8,%9},{%0,%1,%2,%3};"
        : "+f"(c[0]), "+f"(c[1]), "+f"(c[2]), "+f"(c[3])
        : "r"(a[0]), "r"(a[1]), "r"(a[2]), "r"(a[3]), "r"(b0), "r"(b1));
}
__device__ __forceinline__ uint32_t pack2h(float a, float b) {
    __half2 t = __floats2half2_rn(a, b);
    return *reinterpret_cast<uint32_t*>(&t);
}
__device__ __forceinline__ void cpasync16(void* dst, const void* src) {
    asm volatile("cp.async.cg.shared.global [%0], [%1], 16;"
                 :: "r"(saddr(dst)), "l"(src));
}
__device__ __forceinline__ void cp_commit() {
    asm volatile("cp.async.commit_group;" ::: "memory");
}
template <int N> __device__ __forceinline__ void cp_wait() {
    asm volatile("cp.async.wait_group %0;" :: "n"(N) : "memory");
}

// ---------------- h = x + pe (fp32 + fp16) ----------------
__global__ __launch_bounds__(256) void add_pe(const float* __restrict__ x,
                                              float* __restrict__ h,
                                              __half* __restrict__ hf) {
    int row = blockIdx.x;
    int c0  = threadIdx.x * 4;
    const float kf = -9.210340371976184f / (float)DIM;
    float4 xv = *reinterpret_cast<const float4*>(x + (size_t)row * DIM + c0);
    float v[4] = {xv.x, xv.y, xv.z, xv.w};
    float o[4];
#pragma unroll
    for (int e = 0; e < 4; e++) {
        int c = c0 + e;
        float div = expf((float)(c & ~1) * kf);
        float arg = (float)row * div;
        o[e] = v[e] + ((c & 1) ? cosf(arg) : sinf(arg));
    }
    size_t base = (size_t)row * DIM + c0;
    *reinterpret_cast<float4*>(h + base) = make_float4(o[0], o[1], o[2], o[3]);
    *reinterpret_cast<__half2*>(hf + base)     = __floats2half2_rn(o[0], o[1]);
    *reinterpret_cast<__half2*>(hf + base + 2) = __floats2half2_rn(o[2], o[3]);
}

// ---------------- fp16 weight transpose (4 weights): Wt[n,k] = W[k,n] --------
__global__ __launch_bounds__(256) void whalf_t(const float* __restrict__ W0,
                                               const float* __restrict__ W1,
                                               const float* __restrict__ W2,
                                               const float* __restrict__ W3,
                                               __half* __restrict__ outw) {
    __shared__ float t[32][33];
    const float* Ws[4] = {W0, W1, W2, W3};
    const float* W = Ws[blockIdx.z];
    __half* o = outw + (size_t)blockIdx.z * DIM * DIM;
    int k0 = blockIdx.x * 32, n0 = blockIdx.y * 32;
    int tx = threadIdx.x, ty = threadIdx.y;
#pragma unroll
    for (int j = 0; j < 4; j++)
        t[ty + 8 * j][tx] = W[(size_t)(k0 + ty + 8 * j) * DIM + n0 + tx];
    __syncthreads();
#pragma unroll
    for (int j = 0; j < 4; j++)
        o[(size_t)(n0 + ty + 8 * j) * DIM + k0 + tx] =
            __float2half_rn(t[tx][ty + 8 * j]);
}

// ---------------- fused q/k/v GEMM: single fp16 product ----------------
__global__ __launch_bounds__(256, 2) void gemm_qkv(
    const __half* __restrict__ A, const __half* __restrict__ Wf,
    const float* __restrict__ bq, const float* __restrict__ bk,
    const float* __restrict__ bv,
    __half* __restrict__ Qo, __half* __restrict__ Ko, __half* __restrict__ Vo) {
    extern __shared__ __half smq[];
    const int tid  = threadIdx.x;
    const int warp = tid >> 5, lane = tid & 31;
    const int g = lane >> 2, t4 = lane & 3;
    const int lr = lane & 7, sub = lane >> 3;
    const int wm = warp & 3, wn = warp >> 2;
    const int wsel = blockIdx.x >> 3;
    const int n0 = (blockIdx.x & 7) * 128;
    const int m0 = blockIdx.y * 128;
    const __half* B = Wf + (size_t)wsel * DIM * DIM;
    const float* bias = (wsel == 0) ? bq : ((wsel == 1) ? bk : bv);
    __half* C = (wsel == 0) ? Qo : ((wsel == 1) ? Ko : Vo);
    const float osc = (wsel == 0) ? 0.18033688011112042f : 1.0f;  // (1/8)*log2e

    auto load_chunk = [&](int kb, int st) {
        __half* sA = smq + st * 16384;
        __half* sB = sA + 8192;
#pragma unroll
        for (int i = 0; i < 4; i++) {
            int id = tid + i * 256;
            int r = id >> 3, cc = id & 7;
            int sidx = (r * 8 + ((cc ^ r) & 7)) * 8;
            cpasync16(sA + sidx, A + (size_t)(m0 + r) * DIM + kb * 64 + cc * 8);
            cpasync16(sB + sidx, B + (size_t)(n0 + r) * DIM + kb * 64 + cc * 8);
        }
    };

    float acc[2][8][4];
#pragma unroll
    for (int mt = 0; mt < 2; mt++)
#pragma unroll
        for (int nt = 0; nt < 8; nt++)
#pragma unroll
            for (int e = 0; e < 4; e++) acc[mt][nt][e] = 0.f;

    load_chunk(0, 0);
    cp_commit();

    const int NCH = DIM / 64;
    for (int kb = 0; kb < NCH; kb++) {
        int st = kb & 1;
        if (kb + 1 < NCH) { load_chunk(kb + 1, st ^ 1); cp_commit(); cp_wait<1>(); }
        else              { cp_wait<0>(); }
        __syncthreads();
        __half* sA = smq + st * 16384;
        __half* sB = sA + 8192;
#pragma unroll
        for (int kk = 0; kk < 4; kk++) {
            uint32_t af[2][4];
#pragma unroll
            for (int mt = 0; mt < 2; mt++)
                ldsm4(af[mt], saddr(sA + swzi64(wm * 32 + mt * 16 + lr + (sub & 1) * 8,
                                                kk * 16 + (sub >> 1) * 8)));
#pragma unroll
            for (int ntt = 0; ntt < 4; ntt++) {
                uint32_t bfg[4];
                ldsm4(bfg, saddr(sB + swzi64(wn * 64 + ntt * 16 + lr + (sub >> 1) * 8,
                                             kk * 16 + (sub & 1) * 8)));
#pragma unroll
                for (int mt = 0; mt < 2; mt++) {
                    mma_hf(acc[mt][2 * ntt],     af[mt], bfg[0], bfg[1]);
                    mma_hf(acc[mt][2 * ntt + 1], af[mt], bfg[2], bfg[3]);
                }
            }
        }
        __syncthreads();
    }

#pragma unroll
    for (int mt = 0; mt < 2; mt++) {
#pragma unroll
        for (int nt = 0; nt < 8; nt++) {
            int row0 = m0 + wm * 32 + mt * 16 + g;
            int col  = n0 + wn * 64 + nt * 8 + t4 * 2;
            float b0 = bias[col], b1 = bias[col + 1];
            *reinterpret_cast<__half2*>(C + (size_t)row0 * DIM + col) =
                __floats2half2_rn((acc[mt][nt][0] + b0) * osc,
                                  (acc[mt][nt][1] + b1) * osc);
            *reinterpret_cast<__half2*>(C + (size_t)(row0 + 8) * DIM + col) =
                __floats2half2_rn((acc[mt][nt][2] + b0) * osc,
                                  (acc[mt][nt][3] + b1) * osc);
        }
    }
}

// ---------------- out-proj GEMM: single fp16 product, fp32 out ----------------
__global__ __launch_bounds__(256, 2) void gemm_out(
    const __half* __restrict__ A, const __half* __restrict__ B,
    const float* __restrict__ bias, float* __restrict__ Cf) {
    extern __shared__ __half smq[];
    const int tid  = threadIdx.x;
    const int warp = tid >> 5, lane = tid & 31;
    const int g = lane >> 2, t4 = lane & 3;
    const int lr = lane & 7, sub = lane >> 3;
    const int wm = warp & 3, wn = warp >> 2;
    const int m0 = blockIdx.y * 128, n0 = blockIdx.x * 128;

    auto load_chunk = [&](int kb, int st) {
        __half* sA = smq + st * 16384;
        __half* sB = sA + 8192;
#pragma unroll
        for (int i = 0; i < 4; i++) {
            int id = tid + i * 256;
            int r = id >> 3, cc = id & 7;
            int sidx = (r * 8 + ((cc ^ r) & 7)) * 8;
            cpasync16(sA + sidx, A + (size_t)(m0 + r) * DIM + kb * 64 + cc * 8);
            cpasync16(sB + sidx, B + (size_t)(n0 + r) * DIM + kb * 64 + cc * 8);
        }
    };

    float acc[2][8][4];
#pragma unroll
    for (int mt = 0; mt < 2; mt++)
#pragma unroll
        for (int nt = 0; nt < 8; nt++)
#pragma unroll
            for (int e = 0; e < 4; e++) acc[mt][nt][e] = 0.f;

    load_chunk(0, 0);
    cp_commit();

    const int NCH = DIM / 64;
    for (int kb = 0; kb < NCH; kb++) {
        int st = kb & 1;
        if (kb + 1 < NCH) { load_chunk(kb + 1, st ^ 1); cp_commit(); cp_wait<1>(); }
        else              { cp_wait<0>(); }
        __syncthreads();
        __half* sA = smq + st * 16384;
        __half* sB = sA + 8192;
#pragma unroll
        for (int kk = 0; kk < 4; kk++) {
            uint32_t af[2][4];
#pragma unroll
            for (int mt = 0; mt < 2; mt++)
                ldsm4(af[mt], saddr(sA + swzi64(wm * 32 + mt * 16 + lr + (sub & 1) * 8,
                                                kk * 16 + (sub >> 1) * 8)));
#pragma unroll
            for (int ntt = 0; ntt < 4; ntt++) {
                uint32_t bfg[4];
                ldsm4(bfg, saddr(sB + swzi64(wn * 64 + ntt * 16 + lr + (sub >> 1) * 8,
                                             kk * 16 + (sub & 1) * 8)));
#pragma unroll
                for (int mt = 0; mt < 2; mt++) {
                    mma_hf(acc[mt][2 * ntt],     af[mt], bfg[0], bfg[1]);
                    mma_hf(acc[mt][2 * ntt + 1], af[mt], bfg[2], bfg[3]);
                }
            }
        }
        __syncthreads();
    }

#pragma unroll
    for (int mt = 0; mt < 2; mt++) {
#pragma unroll
        for (int nt = 0; nt < 8; nt++) {
            int row0 = m0 + wm * 32 + mt * 16 + g;
            int col  = n0 + wn * 64 + nt * 8 + t4 * 2;
            float b0 = bias[col], b1 = bias[col + 1];
            *reinterpret_cast<float2*>(Cf + (size_t)row0 * DIM + col) =
                make_float2(acc[mt][nt][0] + b0, acc[mt][nt][1] + b1);
            *reinterpret_cast<float2*>(Cf + (size_t)(row0 + 8) * DIM + col) =
                make_float2(acc[mt][nt][2] + b0, acc[mt][nt][3] + b1);
        }
    }
}

// ---------------- flash attention: lazy-rescale softmax ----------------------
// P is computed against a stale row max m_i; rescale of (o,l,m_i) happens only
// when a tile's max exceeds m_i + 8 (warp-vote). Exact: between rescales o and
// l carry a common factor 2^(m_true-m_i) that cancels in o/l. p <= 2^8 in fp16.
__global__ __launch_bounds__(256, 2) void flash_hf(
    const __half* __restrict__ Qf,
    const __half* __restrict__ Kf,
    const __half* __restrict__ Vf,
    __half* __restrict__ Of) {
    extern __shared__ __half smh[];
    __half* sQ = smh;                    // 128 x 64

    const int tid  = threadIdx.x;
    const int warp = tid >> 5, lane = tid & 31;
    const int g = lane >> 2, t4 = lane & 3;
    const int lr = lane & 7, sub = lane >> 3;
    const int rbase = warp * 16;
    const int head  = blockIdx.y;
    const int qt    = blockIdx.x;

    {
        const __half* qb = Qf + (size_t)(qt * 128) * DIM + head * DHEAD;
#pragma unroll
        for (int i = 0; i < 4; i++) {
            int id = tid + i * 256;
            int r = id >> 3, cc = id & 7;
            cpasync16(sQ + (r * 64 + ((cc ^ r) & 7) * 8),
                      qb + (size_t)r * DIM + cc * 8);
        }
    }
    auto load_kv = [&](int t, int st) {
        __half* sK = smh + 8192  + st * 4096;
        __half* sV = smh + 16384 + st * 4096;
        const size_t base = (size_t)(t * 64) * DIM + head * DHEAD;
#pragma unroll
        for (int i = 0; i < 2; i++) {
            int id = tid + i * 256;
            int r = id >> 3, cc = id & 7;
            int sidx = (r * 8 + ((cc ^ r) & 7)) * 8;
            cpasync16(sK + sidx, Kf + base + (size_t)r * DIM + cc * 8);
            cpasync16(sV + sidx, Vf + base + (size_t)r * DIM + cc * 8);
        }
    };

    float m_i[2], l_i[2], o[8][4];
    m_i[0] = m_i[1] = -1e30f;
    l_i[0] = l_i[1] = 0.f;               // per-thread partial (4 cols each row)
#pragma unroll
    for (int nt = 0; nt < 8; nt++)
#pragma unroll
        for (int e = 0; e < 4; e++) o[nt][e] = 0.f;

    const int NT = SEQ / 64;

    load_kv(0, 0);
    cp_commit();

    for (int t = 0; t < NT; t++) {
        int st = t & 1;
        if (t + 1 < NT) { load_kv(t + 1, st ^ 1); cp_commit(); cp_wait<1>(); }
        else            { cp_wait<0>(); }
        __syncthreads();
        __half* sK = smh + 8192  + st * 4096;
        __half* sV = smh + 16384 + st * 4096;

        // ---- S = Q * K^T (q pre-scaled by (1/8)*log2e) ----
        float s[8][4];
#pragma unroll
        for (int nt = 0; nt < 8; nt++)
#pragma unroll
            for (int e = 0; e < 4; e++) s[nt][e] = 0.f;
#pragma unroll
        for (int kk = 0; kk < 4; kk++) {
            uint32_t qf[4];
            ldsm4(qf, saddr(sQ + swzi64(rbase + lr + (sub & 1) * 8,
                                        kk * 16 + (sub >> 1) * 8)));
#pragma unroll
            for (int ntt = 0; ntt < 4; ntt++) {
                uint32_t kf[4];
                ldsm4(kf, saddr(sK + swzi64(ntt * 16 + lr + (sub >> 1) * 8,
                                            kk * 16 + (sub & 1) * 8)));
                mma_hf(s[2 * ntt],     qf, kf[0], kf[1]);
                mma_hf(s[2 * ntt + 1], qf, kf[2], kf[3]);
            }
        }

        // ---- lazy-rescale softmax (log2 domain) ----
        float tmx[2];
#pragma unroll
        for (int r = 0; r < 2; r++) {
            float m = -1e30f;
#pragma unroll
            for (int j = 0; j < 8; j++)
                m = fmaxf(m, fmaxf(s[j][2 * r], s[j][2 * r + 1]));
            tmx[r] = m;
        }
        bool need = (tmx[0] > m_i[0] + 8.f) || (tmx[1] > m_i[1] + 8.f);
        if (__any_sync(0xffffffffu, need)) {        // rare after early tiles
#pragma unroll
            for (int r = 0; r < 2; r++) {
                float m = fmaxf(tmx[r], m_i[r]);
                m = fmaxf(m, __shfl_xor_sync(0xffffffffu, m, 1));
                m = fmaxf(m, __shfl_xor_sync(0xffffffffu, m, 2));
                float corr = ex2f(m_i[r] - m);
                m_i[r] = m;
                l_i[r] *= corr;
#pragma unroll
                for (int nt = 0; nt < 8; nt++) {
                    o[nt][2 * r]     *= corr;
                    o[nt][2 * r + 1] *= corr;
                }
            }
        }
        // P against stable m_i (p <= 2^8; fp16 relative precision unchanged)
        uint32_t pa[8][2];
        __half2 ll0 = __floats2half2_rn(0.f, 0.f);
        __half2 ll1 = ll0;
#pragma unroll
        for (int j = 0; j < 8; j++) {
            pa[j][0] = ex2h2(pack2h(s[j][0] - m_i[0], s[j][1] - m_i[0]));
            pa[j][1] = ex2h2(pack2h(s[j][2] - m_i[1], s[j][3] - m_i[1]));
            ll0 = __hadd2(ll0, *reinterpret_cast<__half2*>(&pa[j][0]));
            ll1 = __hadd2(ll1, *reinterpret_cast<__half2*>(&pa[j][1]));
        }
        l_i[0] += __low2float(ll0) + __high2float(ll0);
        l_i[1] += __low2float(ll1) + __high2float(ll1);

        // ---- O += P * V ----
#pragma unroll
        for (int kk = 0; kk < 4; kk++) {
            int j0 = 2 * kk, j1 = j0 + 1;
            uint32_t aH[4] = {pa[j0][0], pa[j0][1], pa[j1][0], pa[j1][1]};
#pragma unroll
            for (int ntt = 0; ntt < 4; ntt++) {
                uint32_t vf[4];
                ldsm4t(vf, saddr(sV + swzi64(kk * 16 + lr + (sub & 1) * 8,
                                             ntt * 16 + (sub >> 1) * 8)));
                mma_hf(o[2 * ntt],     aH, vf[0], vf[1]);
                mma_hf(o[2 * ntt + 1], aH, vf[2], vf[3]);
            }
        }
        __syncthreads();
    }

    // final l reduction across the 4 lanes sharing each row
#pragma unroll
    for (int r = 0; r < 2; r++) {
        l_i[r] += __shfl_xor_sync(0xffffffffu, l_i[r], 1);
        l_i[r] += __shfl_xor_sync(0xffffffffu, l_i[r], 2);
    }
    float inv0 = 1.f / l_i[0], inv1 = 1.f / l_i[1];
#pragma unroll
    for (int nt = 0; nt < 8; nt++) {
        int row0 = qt * 128 + rbase + g;
        int col  = head * DHEAD + nt * 8 + t4 * 2;
        *reinterpret_cast<__half2*>(Of + (size_t)row0 * DIM + col) =
            __floats2half2_rn(o[nt][0] * inv0, o[nt][1] * inv0);
        *reinterpret_cast<__half2*>(Of + (size_t)(row0 + 8) * DIM + col) =
            __floats2half2_rn(o[nt][2] * inv1, o[nt][3] * inv1);
    }
}

// ---------------- residual + layernorm ----------------
__global__ __launch_bounds__(256) void ln_kernel(const float* __restrict__ h,
                                                 const float* __restrict__ pr,
                                                 const float* __restrict__ gamma,
                                                 const float* __restrict__ beta,
                                                 float* __restrict__ out) {
    __shared__ float red[16];
    __shared__ float s_mu, s_rstd;
    int row = blockIdx.x, tid = threadIdx.x;
    int c0 = tid * 4;
    float4 hv = *reinterpret_cast<const float4*>(h  + (size_t)row * DIM + c0);
    float4 pv = *reinterpret_cast<const float4*>(pr + (size_t)row * DIM + c0);
    float y[4] = {hv.x + pv.x, hv.y + pv.y, hv.z + pv.z, hv.w + pv.w};
    float sum = y[0] + y[1] + y[2] + y[3];
    float sq  = y[0]*y[0] + y[1]*y[1] + y[2]*y[2] + y[3]*y[3];
#pragma unroll
    for (int off = 16; off; off >>= 1) {
        sum += __shfl_xor_sync(0xffffffffu, sum, off);
        sq  += __shfl_xor_sync(0xffffffffu, sq,  off);
    }
    int w = tid >> 5;
    if ((tid & 31) == 0) { red[w] = sum; red[8 + w] = sq; }
    __syncthreads();
    if (tid == 0) {
        float ts = 0.f, tq = 0.f;
        for (int i = 0; i < 8; i++) { ts += red[i]; tq += red[8 + i]; }
        float mu = ts / (float)DIM;
        s_mu   = mu;
        s_rstd = rsqrtf(tq / (float)DIM - mu * mu + 1e-5f);
    }
    __syncthreads();
    float4 gv = *reinterpret_cast<const float4*>(gamma + c0);
    float4 bv = *reinterpret_cast<const float4*>(beta  + c0);
    float mu = s_mu, rs = s_rstd;
    float4 ov;
    ov.x = (y[0] - mu) * rs * gv.x + bv.x;
    ov.y = (y[1] - mu) * rs * gv.y + bv.y;
    ov.z = (y[2] - mu) * rs * gv.z + bv.z;
    ov.w = (y[3] - mu) * rs * gv.w + bv.w;
    *reinterpret_cast<float4*>(out + (size_t)row * DIM + c0) = ov;
}

// ---------------------------------------------------------------------------
extern "C" void kernel_launch(void* const* d_in, const int* in_sizes, int n_in,
                              void* d_out, int out_size) {
    (void)in_sizes; (void)n_in; (void)out_size;
    const float* x     = (const float*)d_in[0];
    const float* Wq    = (const float*)d_in[1];
    const float* bq    = (const float*)d_in[2];
    const float* Wk    = (const float*)d_in[3];
    const float* bk    = (const float*)d_in[4];
    const float* Wv    = (const float*)d_in[5];
    const float* bv    = (const float*)d_in[6];
    const float* Wo    = (const float*)d_in[7];
    const float* bo    = (const float*)d_in[8];
    const float* gamma = (const float*)d_in[9];
    const float* beta  = (const float*)d_in[10];
    float* out = (float*)d_out;

    void* p;
    cudaGetSymbolAddress(&p, g_h);    float* h    = (float*)p;
    cudaGetSymbolAddress(&p, g_proj); float* proj = (float*)p;
    cudaGetSymbolAddress(&p, g_hf);   __half* hf = (__half*)p;
    cudaGetSymbolAddress(&p, g_wf);   __half* wf = (__half*)p;
    cudaGetSymbolAddress(&p, g_qf);   __half* qf = (__half*)p;
    cudaGetSymbolAddress(&p, g_kf);   __half* kf = (__half*)p;
    cudaGetSymbolAddress(&p, g_vf);   __half* vf = (__half*)p;
    cudaGetSymbolAddress(&p, g_aof);  __half* aof = (__half*)p;

    const int SMEM_G = 65536;            // 2 stages x 32KB
    const int SMEM_F = 49152;            // Q 16KB + (K+V) x 2 stages x 8KB
    cudaFuncSetAttribute(gemm_qkv,
                         cudaFuncAttributeMaxDynamicSharedMemorySize, SMEM_G);
    cudaFuncSetAttribute(gemm_out,
                         cudaFuncAttributeMaxDynamicSharedMemorySize, SMEM_G);
    cudaFuncSetAttribute(flash_hf,
                         cudaFuncAttributeMaxDynamicSharedMemorySize, SMEM_F);

    add_pe<<<SEQ, 256>>>(x, h, hf);
    whalf_t<<<dim3(DIM / 32, DIM / 32, 4), dim3(32, 8)>>>(Wq, Wk, Wv, Wo, wf);

    gemm_qkv<<<dim3(24, SEQ / 128), 256, SMEM_G>>>(hf, wf, bq, bk, bv,
                                                   qf, kf, vf);

    flash_hf<<<dim3(SEQ / 128, NHEAD), 256, SMEM_F>>>(qf, kf, vf, aof);

    gemm_out<<<dim3(DIM / 128, SEQ / 128), 256, SMEM_G>>>(
        aof, wf + 3 * (size_t)DIM * DIM, bo, proj);

    ln_kernel<<<SEQ, 256>>>(h, proj, gamma, beta, out);
}

// round 13
// speedup vs baseline: 1.1027x; 1.0456x over previous
#include <cuda_runtime.h>
#include <cuda_bf16.h>
#include <cuda_fp16.h>
#include <math.h>
#include <stdint.h>

#define SEQ   4096
#define DIM   1024
#define NHEAD 16
#define DHEAD 64

// ---------------- scratch (no cudaMalloc allowed) ----------------
__device__ float  g_h   [SEQ*DIM];     // x + pe (fp32, residual)
__device__ float  g_proj[SEQ*DIM];     // final projection out (fp32)
__device__ __half g_hf[SEQ*DIM];       // x + pe (fp16, qkv GEMM input)
__device__ __half g_wf[4][DIM*DIM];    // Wq/Wk/Wv/Wo fp16, TRANSPOSED [N,K]
__device__ __half g_qf[SEQ*DIM], g_kf[SEQ*DIM], g_vf[SEQ*DIM];
__device__ __half g_aof[SEQ*DIM];      // attention out (fp16)

// ---------------- helpers ----------------
__device__ __forceinline__ uint32_t saddr(const void* p) {
    return (uint32_t)__cvta_generic_to_shared(p);
}
__device__ __forceinline__ float ex2f(float x) {
    float y; asm("ex2.approx.f32 %0, %1;" : "=f"(y) : "f"(x)); return y;
}
__device__ __forceinline__ uint32_t ex2h2(uint32_t x) {
    uint32_t y; asm("ex2.approx.f16x2 %0, %1;" : "=r"(y) : "r"(x)); return y;
}
__device__ __forceinline__ int swzi64(int row, int col) {
    return row * 64 + ((((col >> 3) ^ row) & 7) << 3);
}
__device__ __forceinline__ void ldsm4(uint32_t* r, uint32_t a) {
    asm volatile("ldmatrix.sync.aligned.m8n8.x4.shared.b16 {%0,%1,%2,%3},[%4];"
                 : "=r"(r[0]), "=r"(r[1]), "=r"(r[2]), "=r"(r[3]) : "r"(a));
}
__device__ __forceinline__ void ldsm4t(uint32_t* r, uint32_t a) {
    asm volatile("ldmatrix.sync.aligned.m8n8.x4.trans.shared.b16 {%0,%1,%2,%3},[%4];"
                 : "=r"(r[0]), "=r"(r[1]), "=r"(r[2]), "=r"(r[3]) : "r"(a));
}
__device__ __forceinline__ void mma_hf(float* c, const uint32_t* a,
                                       uint32_t b0, uint32_t b1) {
    asm volatile(
        "mma.sync.aligned.m16n8k16.row.col.f32.f16.f16.f32 "
        "{%0,%1,%2,%3},{%4,%5,%6,%7},{%8,%9},{%0,%1,%2,%3};"
        : "+f"(c[0]), "+f"(c[1]), "+f"(c[2]), "+f"(c[3])
        : "r"(a[0]), "r"(a[1]), "r"(a[2]), "r"(a[3]), "r"(b0), "r"(b1));
}
__device__ __forceinline__ uint32_t pack2h(float a, float b) {
    __half2 t = __floats2half2_rn(a, b);
    return *reinterpret_cast<uint32_t*>(&t);
}
__device__ __forceinline__ void cpasync16(void* dst, const void* src) {
    asm volatile("cp.async.cg.shared.global [%0], [%1], 16;"
                 :: "r"(saddr(dst)), "l"(src));
}
__device__ __forceinline__ void cp_commit() {
    asm volatile("cp.async.commit_group;" ::: "memory");
}
template <int N> __device__ __forceinline__ void cp_wait() {
    asm volatile("cp.async.wait_group %0;" :: "n"(N) : "memory");
}

// ---------------- h = x + pe (fp32 + fp16) ----------------
__global__ __launch_bounds__(256) void add_pe(const float* __restrict__ x,
                                              float* __restrict__ h,
                                              __half* __restrict__ hf) {
    int row = blockIdx.x;
    int c0  = threadIdx.x * 4;
    const float kf = -9.210340371976184f / (float)DIM;
    float4 xv = *reinterpret_cast<const float4*>(x + (size_t)row * DIM + c0);
    float v[4] = {xv.x, xv.y, xv.z, xv.w};
    float o[4];
#pragma unroll
    for (int e = 0; e < 4; e++) {
        int c = c0 + e;
        float div = expf((float)(c & ~1) * kf);
        float arg = (float)row * div;
        o[e] = v[e] + ((c & 1) ? cosf(arg) : sinf(arg));
    }
    size_t base = (size_t)row * DIM + c0;
    *reinterpret_cast<float4*>(h + base) = make_float4(o[0], o[1], o[2], o[3]);
    *reinterpret_cast<__half2*>(hf + base)     = __floats2half2_rn(o[0], o[1]);
    *reinterpret_cast<__half2*>(hf + base + 2) = __floats2half2_rn(o[2], o[3]);
}

// ---------------- fp16 weight transpose (4 weights): Wt[n,k] = W[k,n] --------
__global__ __launch_bounds__(256) void whalf_t(const float* __restrict__ W0,
                                               const float* __restrict__ W1,
                                               const float* __restrict__ W2,
                                               const float* __restrict__ W3,
                                               __half* __restrict__ outw) {
    __shared__ float t[32][33];
    const float* Ws[4] = {W0, W1, W2, W3};
    const float* W = Ws[blockIdx.z];
    __half* o = outw + (size_t)blockIdx.z * DIM * DIM;
    int k0 = blockIdx.x * 32, n0 = blockIdx.y * 32;
    int tx = threadIdx.x, ty = threadIdx.y;
#pragma unroll
    for (int j = 0; j < 4; j++)
        t[ty + 8 * j][tx] = W[(size_t)(k0 + ty + 8 * j) * DIM + n0 + tx];
    __syncthreads();
#pragma unroll
    for (int j = 0; j < 4; j++)
        o[(size_t)(n0 + ty + 8 * j) * DIM + k0 + tx] =
            __float2half_rn(t[tx][ty + 8 * j]);
}

// ---------------- fused q/k/v GEMM: single fp16 product ----------------
__global__ __launch_bounds__(256, 2) void gemm_qkv(
    const __half* __restrict__ A, const __half* __restrict__ Wf,
    const float* __restrict__ bq, const float* __restrict__ bk,
    const float* __restrict__ bv,
    __half* __restrict__ Qo, __half* __restrict__ Ko, __half* __restrict__ Vo) {
    extern __shared__ __half smq[];
    const int tid  = threadIdx.x;
    const int warp = tid >> 5, lane = tid & 31;
    const int g = lane >> 2, t4 = lane & 3;
    const int lr = lane & 7, sub = lane >> 3;
    const int wm = warp & 3, wn = warp >> 2;
    const int wsel = blockIdx.x >> 3;
    const int n0 = (blockIdx.x & 7) * 128;
    const int m0 = blockIdx.y * 128;
    const __half* B = Wf + (size_t)wsel * DIM * DIM;
    const float* bias = (wsel == 0) ? bq : ((wsel == 1) ? bk : bv);
    __half* C = (wsel == 0) ? Qo : ((wsel == 1) ? Ko : Vo);
    const float osc = (wsel == 0) ? 0.18033688011112042f : 1.0f;  // (1/8)*log2e

    auto load_chunk = [&](int kb, int st) {
        __half* sA = smq + st * 16384;
        __half* sB = sA + 8192;
#pragma unroll
        for (int i = 0; i < 4; i++) {
            int id = tid + i * 256;
            int r = id >> 3, cc = id & 7;
            int sidx = (r * 8 + ((cc ^ r) & 7)) * 8;
            cpasync16(sA + sidx, A + (size_t)(m0 + r) * DIM + kb * 64 + cc * 8);
            cpasync16(sB + sidx, B + (size_t)(n0 + r) * DIM + kb * 64 + cc * 8);
        }
    };

    float acc[2][8][4];
#pragma unroll
    for (int mt = 0; mt < 2; mt++)
#pragma unroll
        for (int nt = 0; nt < 8; nt++)
#pragma unroll
            for (int e = 0; e < 4; e++) acc[mt][nt][e] = 0.f;

    load_chunk(0, 0);
    cp_commit();

    const int NCH = DIM / 64;
    for (int kb = 0; kb < NCH; kb++) {
        int st = kb & 1;
        if (kb + 1 < NCH) { load_chunk(kb + 1, st ^ 1); cp_commit(); cp_wait<1>(); }
        else              { cp_wait<0>(); }
        __syncthreads();
        __half* sA = smq + st * 16384;
        __half* sB = sA + 8192;
#pragma unroll
        for (int kk = 0; kk < 4; kk++) {
            uint32_t af[2][4];
#pragma unroll
            for (int mt = 0; mt < 2; mt++)
                ldsm4(af[mt], saddr(sA + swzi64(wm * 32 + mt * 16 + lr + (sub & 1) * 8,
                                                kk * 16 + (sub >> 1) * 8)));
#pragma unroll
            for (int ntt = 0; ntt < 4; ntt++) {
                uint32_t bfg[4];
                ldsm4(bfg, saddr(sB + swzi64(wn * 64 + ntt * 16 + lr + (sub >> 1) * 8,
                                             kk * 16 + (sub & 1) * 8)));
#pragma unroll
                for (int mt = 0; mt < 2; mt++) {
                    mma_hf(acc[mt][2 * ntt],     af[mt], bfg[0], bfg[1]);
                    mma_hf(acc[mt][2 * ntt + 1], af[mt], bfg[2], bfg[3]);
                }
            }
        }
        __syncthreads();
    }

#pragma unroll
    for (int mt = 0; mt < 2; mt++) {
#pragma unroll
        for (int nt = 0; nt < 8; nt++) {
            int row0 = m0 + wm * 32 + mt * 16 + g;
            int col  = n0 + wn * 64 + nt * 8 + t4 * 2;
            float b0 = bias[col], b1 = bias[col + 1];
            *reinterpret_cast<__half2*>(C + (size_t)row0 * DIM + col) =
                __floats2half2_rn((acc[mt][nt][0] + b0) * osc,
                                  (acc[mt][nt][1] + b1) * osc);
            *reinterpret_cast<__half2*>(C + (size_t)(row0 + 8) * DIM + col) =
                __floats2half2_rn((acc[mt][nt][2] + b0) * osc,
                                  (acc[mt][nt][3] + b1) * osc);
        }
    }
}

// ---------------- out-proj GEMM: single fp16 product, fp32 out ----------------
__global__ __launch_bounds__(256, 2) void gemm_out(
    const __half* __restrict__ A, const __half* __restrict__ B,
    const float* __restrict__ bias, float* __restrict__ Cf) {
    extern __shared__ __half smq[];
    const int tid  = threadIdx.x;
    const int warp = tid >> 5, lane = tid & 31;
    const int g = lane >> 2, t4 = lane & 3;
    const int lr = lane & 7, sub = lane >> 3;
    const int wm = warp & 3, wn = warp >> 2;
    const int m0 = blockIdx.y * 128, n0 = blockIdx.x * 128;

    auto load_chunk = [&](int kb, int st) {
        __half* sA = smq + st * 16384;
        __half* sB = sA + 8192;
#pragma unroll
        for (int i = 0; i < 4; i++) {
            int id = tid + i * 256;
            int r = id >> 3, cc = id & 7;
            int sidx = (r * 8 + ((cc ^ r) & 7)) * 8;
            cpasync16(sA + sidx, A + (size_t)(m0 + r) * DIM + kb * 64 + cc * 8);
            cpasync16(sB + sidx, B + (size_t)(n0 + r) * DIM + kb * 64 + cc * 8);
        }
    };

    float acc[2][8][4];
#pragma unroll
    for (int mt = 0; mt < 2; mt++)
#pragma unroll
        for (int nt = 0; nt < 8; nt++)
#pragma unroll
            for (int e = 0; e < 4; e++) acc[mt][nt][e] = 0.f;

    load_chunk(0, 0);
    cp_commit();

    const int NCH = DIM / 64;
    for (int kb = 0; kb < NCH; kb++) {
        int st = kb & 1;
        if (kb + 1 < NCH) { load_chunk(kb + 1, st ^ 1); cp_commit(); cp_wait<1>(); }
        else              { cp_wait<0>(); }
        __syncthreads();
        __half* sA = smq + st * 16384;
        __half* sB = sA + 8192;
#pragma unroll
        for (int kk = 0; kk < 4; kk++) {
            uint32_t af[2][4];
#pragma unroll
            for (int mt = 0; mt < 2; mt++)
                ldsm4(af[mt], saddr(sA + swzi64(wm * 32 + mt * 16 + lr + (sub & 1) * 8,
                                                kk * 16 + (sub >> 1) * 8)));
#pragma unroll
            for (int ntt = 0; ntt < 4; ntt++) {
                uint32_t bfg[4];
                ldsm4(bfg, saddr(sB + swzi64(wn * 64 + ntt * 16 + lr + (sub >> 1) * 8,
                                             kk * 16 + (sub & 1) * 8)));
#pragma unroll
                for (int mt = 0; mt < 2; mt++) {
                    mma_hf(acc[mt][2 * ntt],     af[mt], bfg[0], bfg[1]);
                    mma_hf(acc[mt][2 * ntt + 1], af[mt], bfg[2], bfg[3]);
                }
            }
        }
        __syncthreads();
    }

#pragma unroll
    for (int mt = 0; mt < 2; mt++) {
#pragma unroll
        for (int nt = 0; nt < 8; nt++) {
            int row0 = m0 + wm * 32 + mt * 16 + g;
            int col  = n0 + wn * 64 + nt * 8 + t4 * 2;
            float b0 = bias[col], b1 = bias[col + 1];
            *reinterpret_cast<float2*>(Cf + (size_t)row0 * DIM + col) =
                make_float2(acc[mt][nt][0] + b0, acc[mt][nt][1] + b1);
            *reinterpret_cast<float2*>(Cf + (size_t)(row0 + 8) * DIM + col) =
                make_float2(acc[mt][nt][2] + b0, acc[mt][nt][3] + b1);
        }
    }
}

// ---------------- flash attention: 4 warps x 32 q-rows (K/V fragment reuse) --
// Each K/V ldsm feeds 2 m-tiles -> smem bytes per FLOP down 44%.
// smem (halfs): Q[0..8191] | K st{0,1} @8192+st*4096 | V st{0,1} @16384+st*4096
__global__ __launch_bounds__(128, 2) void flash_hf(
    const __half* __restrict__ Qf,
    const __half* __restrict__ Kf,
    const __half* __restrict__ Vf,
    __half* __restrict__ Of) {
    extern __shared__ __half smh[];
    __half* sQ = smh;                    // 128 x 64

    const int tid  = threadIdx.x;
    const int warp = tid >> 5, lane = tid & 31;
    const int g = lane >> 2, t4 = lane & 3;
    const int lr = lane & 7, sub = lane >> 3;
    const int head  = blockIdx.y;
    const int qt    = blockIdx.x;

    {
        const __half* qb = Qf + (size_t)(qt * 128) * DIM + head * DHEAD;
#pragma unroll
        for (int i = 0; i < 8; i++) {
            int id = tid + i * 128;
            int r = id >> 3, cc = id & 7;
            cpasync16(sQ + (r * 64 + ((cc ^ r) & 7) * 8),
                      qb + (size_t)r * DIM + cc * 8);
        }
    }
    auto load_kv = [&](int t, int st) {
        __half* sK = smh + 8192  + st * 4096;
        __half* sV = smh + 16384 + st * 4096;
        const size_t base = (size_t)(t * 64) * DIM + head * DHEAD;
#pragma unroll
        for (int i = 0; i < 4; i++) {
            int id = tid + i * 128;          // 0..511
            int r = id >> 3, cc = id & 7;
            int sidx = (r * 8 + ((cc ^ r) & 7)) * 8;
            cpasync16(sK + sidx, Kf + base + (size_t)r * DIM + cc * 8);
            cpasync16(sV + sidx, Vf + base + (size_t)r * DIM + cc * 8);
        }
    };

    float m_i[2][2], l_i[2][2], o[2][8][4];
#pragma unroll
    for (int mt = 0; mt < 2; mt++) {
        m_i[mt][0] = m_i[mt][1] = -1e30f;
        l_i[mt][0] = l_i[mt][1] = 0.f;
#pragma unroll
        for (int nt = 0; nt < 8; nt++)
#pragma unroll
            for (int e = 0; e < 4; e++) o[mt][nt][e] = 0.f;
    }

    const int NT = SEQ / 64;

    load_kv(0, 0);
    cp_commit();

    for (int t = 0; t < NT; t++) {
        int st = t & 1;
        if (t + 1 < NT) { load_kv(t + 1, st ^ 1); cp_commit(); cp_wait<1>(); }
        else            { cp_wait<0>(); }
        __syncthreads();
        __half* sK = smh + 8192  + st * 4096;
        __half* sV = smh + 16384 + st * 4096;

        // ---- S = Q * K^T (q pre-scaled); K fragments shared by 2 m-tiles ----
        float s[2][8][4];
#pragma unroll
        for (int mt = 0; mt < 2; mt++)
#pragma unroll
            for (int nt = 0; nt < 8; nt++)
#pragma unroll
                for (int e = 0; e < 4; e++) s[mt][nt][e] = 0.f;
#pragma unroll
        for (int kk = 0; kk < 4; kk++) {
            uint32_t qf[2][4];
#pragma unroll
            for (int mt = 0; mt < 2; mt++)
                ldsm4(qf[mt], saddr(sQ + swzi64(warp * 32 + mt * 16 + lr + (sub & 1) * 8,
                                                kk * 16 + (sub >> 1) * 8)));
#pragma unroll
            for (int ntt = 0; ntt < 4; ntt++) {
                uint32_t kf[4];
                ldsm4(kf, saddr(sK + swzi64(ntt * 16 + lr + (sub >> 1) * 8,
                                            kk * 16 + (sub & 1) * 8)));
#pragma unroll
                for (int mt = 0; mt < 2; mt++) {
                    mma_hf(s[mt][2 * ntt],     qf[mt], kf[0], kf[1]);
                    mma_hf(s[mt][2 * ntt + 1], qf[mt], kf[2], kf[3]);
                }
            }
        }

        // ---- lazy-rescale softmax (log2 domain) ----
        float tmx[2][2];
        bool need = false;
#pragma unroll
        for (int mt = 0; mt < 2; mt++)
#pragma unroll
            for (int r = 0; r < 2; r++) {
                float m = -1e30f;
#pragma unroll
                for (int j = 0; j < 8; j++)
                    m = fmaxf(m, fmaxf(s[mt][j][2 * r], s[mt][j][2 * r + 1]));
                tmx[mt][r] = m;
                need = need || (m > m_i[mt][r] + 8.f);
            }
        if (__any_sync(0xffffffffu, need)) {        // rare after early tiles
#pragma unroll
            for (int mt = 0; mt < 2; mt++)
#pragma unroll
                for (int r = 0; r < 2; r++) {
                    float m = fmaxf(tmx[mt][r], m_i[mt][r]);
                    m = fmaxf(m, __shfl_xor_sync(0xffffffffu, m, 1));
                    m = fmaxf(m, __shfl_xor_sync(0xffffffffu, m, 2));
                    float corr = ex2f(m_i[mt][r] - m);
                    m_i[mt][r] = m;
                    l_i[mt][r] *= corr;
#pragma unroll
                    for (int nt = 0; nt < 8; nt++) {
                        o[mt][nt][2 * r]     *= corr;
                        o[mt][nt][2 * r + 1] *= corr;
                    }
                }
        }
        // P against stable m_i (p <= 2^8; fp16 relative precision unchanged)
        uint32_t pa[2][8][2];
#pragma unroll
        for (int mt = 0; mt < 2; mt++) {
            __half2 ll0 = __floats2half2_rn(0.f, 0.f);
            __half2 ll1 = ll0;
#pragma unroll
            for (int j = 0; j < 8; j++) {
                pa[mt][j][0] = ex2h2(pack2h(s[mt][j][0] - m_i[mt][0],
                                            s[mt][j][1] - m_i[mt][0]));
                pa[mt][j][1] = ex2h2(pack2h(s[mt][j][2] - m_i[mt][1],
                                            s[mt][j][3] - m_i[mt][1]));
                ll0 = __hadd2(ll0, *reinterpret_cast<__half2*>(&pa[mt][j][0]));
                ll1 = __hadd2(ll1, *reinterpret_cast<__half2*>(&pa[mt][j][1]));
            }
            l_i[mt][0] += __low2float(ll0) + __high2float(ll0);
            l_i[mt][1] += __low2float(ll1) + __high2float(ll1);
        }

        // ---- O += P * V; V fragments shared by 2 m-tiles ----
#pragma unroll
        for (int kk = 0; kk < 4; kk++) {
            int j0 = 2 * kk, j1 = j0 + 1;
            uint32_t aH[2][4];
#pragma unroll
            for (int mt = 0; mt < 2; mt++) {
                aH[mt][0] = pa[mt][j0][0]; aH[mt][1] = pa[mt][j0][1];
                aH[mt][2] = pa[mt][j1][0]; aH[mt][3] = pa[mt][j1][1];
            }
#pragma unroll
            for (int ntt = 0; ntt < 4; ntt++) {
                uint32_t vf[4];
                ldsm4t(vf, saddr(sV + swzi64(kk * 16 + lr + (sub & 1) * 8,
                                             ntt * 16 + (sub >> 1) * 8)));
#pragma unroll
                for (int mt = 0; mt < 2; mt++) {
                    mma_hf(o[mt][2 * ntt],     aH[mt], vf[0], vf[1]);
                    mma_hf(o[mt][2 * ntt + 1], aH[mt], vf[2], vf[3]);
                }
            }
        }
        __syncthreads();
    }

    // final l reduction across the 4 lanes sharing each row, then store
#pragma unroll
    for (int mt = 0; mt < 2; mt++) {
#pragma unroll
        for (int r = 0; r < 2; r++) {
            l_i[mt][r] += __shfl_xor_sync(0xffffffffu, l_i[mt][r], 1);
            l_i[mt][r] += __shfl_xor_sync(0xffffffffu, l_i[mt][r], 2);
        }
        float inv0 = 1.f / l_i[mt][0], inv1 = 1.f / l_i[mt][1];
#pragma unroll
        for (int nt = 0; nt < 8; nt++) {
            int row0 = qt * 128 + warp * 32 + mt * 16 + g;
            int col  = head * DHEAD + nt * 8 + t4 * 2;
            *reinterpret_cast<__half2*>(Of + (size_t)row0 * DIM + col) =
                __floats2half2_rn(o[mt][nt][0] * inv0, o[mt][nt][1] * inv0);
            *reinterpret_cast<__half2*>(Of + (size_t)(row0 + 8) * DIM + col) =
                __floats2half2_rn(o[mt][nt][2] * inv1, o[mt][nt][3] * inv1);
        }
    }
}

// ---------------- residual + layernorm ----------------
__global__ __launch_bounds__(256) void ln_kernel(const float* __restrict__ h,
                                                 const float* __restrict__ pr,
                                                 const float* __restrict__ gamma,
                                                 const float* __restrict__ beta,
                                                 float* __restrict__ out) {
    __shared__ float red[16];
    __shared__ float s_mu, s_rstd;
    int row = blockIdx.x, tid = threadIdx.x;
    int c0 = tid * 4;
    float4 hv = *reinterpret_cast<const float4*>(h  + (size_t)row * DIM + c0);
    float4 pv = *reinterpret_cast<const float4*>(pr + (size_t)row * DIM + c0);
    float y[4] = {hv.x + pv.x, hv.y + pv.y, hv.z + pv.z, hv.w + pv.w};
    float sum = y[0] + y[1] + y[2] + y[3];
    float sq  = y[0]*y[0] + y[1]*y[1] + y[2]*y[2] + y[3]*y[3];
#pragma unroll
    for (int off = 16; off; off >>= 1) {
        sum += __shfl_xor_sync(0xffffffffu, sum, off);
        sq  += __shfl_xor_sync(0xffffffffu, sq,  off);
    }
    int w = tid >> 5;
    if ((tid & 31) == 0) { red[w] = sum; red[8 + w] = sq; }
    __syncthreads();
    if (tid == 0) {
        float ts = 0.f, tq = 0.f;
        for (int i = 0; i < 8; i++) { ts += red[i]; tq += red[8 + i]; }
        float mu = ts / (float)DIM;
        s_mu   = mu;
        s_rstd = rsqrtf(tq / (float)DIM - mu * mu + 1e-5f);
    }
    __syncthreads();
    float4 gv = *reinterpret_cast<const float4*>(gamma + c0);
    float4 bv = *reinterpret_cast<const float4*>(beta  + c0);
    float mu = s_mu, rs = s_rstd;
    float4 ov;
    ov.x = (y[0] - mu) * rs * gv.x + bv.x;
    ov.y = (y[1] - mu) * rs * gv.y + bv.y;
    ov.z = (y[2] - mu) * rs * gv.z + bv.z;
    ov.w = (y[3] - mu) * rs * gv.w + bv.w;
    *reinterpret_cast<float4*>(out + (size_t)row * DIM + c0) = ov;
}

// ---------------------------------------------------------------------------
extern "C" void kernel_launch(void* const* d_in, const int* in_sizes, int n_in,
                              void* d_out, int out_size) {
    (void)in_sizes; (void)n_in; (void)out_size;
    const float* x     = (const float*)d_in[0];
    const float* Wq    = (const float*)d_in[1];
    const float* bq    = (const float*)d_in[2];
    const float* Wk    = (const float*)d_in[3];
    const float* bk    = (const float*)d_in[4];
    const float* Wv    = (const float*)d_in[5];
    const float* bv    = (const float*)d_in[6];
    const float* Wo    = (const float*)d_in[7];
    const float* bo    = (const float*)d_in[8];
    const float* gamma = (const float*)d_in[9];
    const float* beta  = (const float*)d_in[10];
    float* out = (float*)d_out;

    void* p;
    cudaGetSymbolAddress(&p, g_h);    float* h    = (float*)p;
    cudaGetSymbolAddress(&p, g_proj); float* proj = (float*)p;
    cudaGetSymbolAddress(&p, g_hf);   __half* hf = (__half*)p;
    cudaGetSymbolAddress(&p, g_wf);   __half* wf = (__half*)p;
    cudaGetSymbolAddress(&p, g_qf);   __half* qf = (__half*)p;
    cudaGetSymbolAddress(&p, g_kf);   __half* kf = (__half*)p;
    cudaGetSymbolAddress(&p, g_vf);   __half* vf = (__half*)p;
    cudaGetSymbolAddress(&p, g_aof);  __half* aof = (__half*)p;

    const int SMEM_G = 65536;            // 2 stages x 32KB
    const int SMEM_F = 49152;            // Q 16KB + (K+V) x 2 stages x 8KB
    cudaFuncSetAttribute(gemm_qkv,
                         cudaFuncAttributeMaxDynamicSharedMemorySize, SMEM_G);
    cudaFuncSetAttribute(gemm_out,
                         cudaFuncAttributeMaxDynamicSharedMemorySize, SMEM_G);
    cudaFuncSetAttribute(flash_hf,
                         cudaFuncAttributeMaxDynamicSharedMemorySize, SMEM_F);

    add_pe<<<SEQ, 256>>>(x, h, hf);
    whalf_t<<<dim3(DIM / 32, DIM / 32, 4), dim3(32, 8)>>>(Wq, Wk, Wv, Wo, wf);

    gemm_qkv<<<dim3(24, SEQ / 128), 256, SMEM_G>>>(hf, wf, bq, bk, bv,
                                                   qf, kf, vf);

    flash_hf<<<dim3(SEQ / 128, NHEAD), 128, SMEM_F>>>(qf, kf, vf, aof);

    gemm_out<<<dim3(DIM / 128, SEQ / 128), 256, SMEM_G>>>(
        aof, wf + 3 * (size_t)DIM * DIM, bo, proj);

    ln_kernel<<<SEQ, 256>>>(h, proj, gamma, beta, out);
}

// round 14
// speedup vs baseline: 1.1151x; 1.0112x over previous
#include <cuda_runtime.h>
#include <cuda_bf16.h>
#include <cuda_fp16.h>
#include <math.h>
#include <stdint.h>

#define SEQ   4096
#define DIM   1024
#define NHEAD 16
#define DHEAD 64

// ---------------- scratch (no cudaMalloc allowed) ----------------
__device__ float  g_h   [SEQ*DIM];     // x + pe (fp32, residual)
__device__ float  g_proj[SEQ*DIM];     // final projection out (fp32)
__device__ __half g_hf[SEQ*DIM];       // x + pe (fp16, qkv GEMM input)
__device__ __half g_wf[4][DIM*DIM];    // Wq/Wk/Wv/Wo fp16, TRANSPOSED [N,K]
__device__ __half g_qf[SEQ*DIM], g_kf[SEQ*DIM], g_vf[SEQ*DIM];
__device__ __half g_aof[SEQ*DIM];      // attention out (fp16)

// ---------------- helpers ----------------
__device__ __forceinline__ uint32_t saddr(const void* p) {
    return (uint32_t)__cvta_generic_to_shared(p);
}
__device__ __forceinline__ float ex2f(float x) {
    float y; asm("ex2.approx.f32 %0, %1;" : "=f"(y) : "f"(x)); return y;
}
__device__ __forceinline__ uint32_t ex2h2(uint32_t x) {
    uint32_t y; asm("ex2.approx.f16x2 %0, %1;" : "=r"(y) : "r"(x)); return y;
}
__device__ __forceinline__ int swzi64(int row, int col) {
    return row * 64 + ((((col >> 3) ^ row) & 7) << 3);
}
__device__ __forceinline__ void ldsm4(uint32_t* r, uint32_t a) {
    asm volatile("ldmatrix.sync.aligned.m8n8.x4.shared.b16 {%0,%1,%2,%3},[%4];"
                 : "=r"(r[0]), "=r"(r[1]), "=r"(r[2]), "=r"(r[3]) : "r"(a));
}
__device__ __forceinline__ void ldsm4t(uint32_t* r, uint32_t a) {
    asm volatile("ldmatrix.sync.aligned.m8n8.x4.trans.shared.b16 {%0,%1,%2,%3},[%4];"
                 : "=r"(r[0]), "=r"(r[1]), "=r"(r[2]), "=r"(r[3]) : "r"(a));
}
__device__ __forceinline__ void mma_hf(float* c, const uint32_t* a,
                                       uint32_t b0, uint32_t b1) {
    asm volatile(
        "mma.sync.aligned.m16n8k16.row.col.f32.f16.f16.f32 "
        "{%0,%1,%2,%3},{%4,%5,%6,%7},{%8,%9},{%0,%1,%2,%3};"
        : "+f"(c[0]), "+f"(c[1]), "+f"(c[2]), "+f"(c[3])
        : "r"(a[0]), "r"(a[1]), "r"(a[2]), "r"(a[3]), "r"(b0), "r"(b1));
}
__device__ __forceinline__ uint32_t pack2h(float a, float b) {
    __half2 t = __floats2half2_rn(a, b);
    return *reinterpret_cast<uint32_t*>(&t);
}
__device__ __forceinline__ void cpasync16(void* dst, const void* src) {
    asm volatile("cp.async.cg.shared.global [%0], [%1], 16;"
                 :: "r"(saddr(dst)), "l"(src));
}
__device__ __forceinline__ void cp_commit() {
    asm volatile("cp.async.commit_group;" ::: "memory");
}
template <int N> __device__ __forceinline__ void cp_wait() {
    asm volatile("cp.async.wait_group %0;" :: "n"(N) : "memory");
}

// ---------------- h = x + pe (fp32 + fp16) ----------------
__global__ __launch_bounds__(256) void add_pe(const float* __restrict__ x,
                                              float* __restrict__ h,
                                              __half* __restrict__ hf) {
    int row = blockIdx.x;
    int c0  = threadIdx.x * 4;
    const float kf = -9.210340371976184f / (float)DIM;
    float4 xv = *reinterpret_cast<const float4*>(x + (size_t)row * DIM + c0);
    float v[4] = {xv.x, xv.y, xv.z, xv.w};
    float o[4];
#pragma unroll
    for (int e = 0; e < 4; e++) {
        int c = c0 + e;
        float div = expf((float)(c & ~1) * kf);
        float arg = (float)row * div;
        o[e] = v[e] + ((c & 1) ? cosf(arg) : sinf(arg));
    }
    size_t base = (size_t)row * DIM + c0;
    *reinterpret_cast<float4*>(h + base) = make_float4(o[0], o[1], o[2], o[3]);
    *reinterpret_cast<__half2*>(hf + base)     = __floats2half2_rn(o[0], o[1]);
    *reinterpret_cast<__half2*>(hf + base + 2) = __floats2half2_rn(o[2], o[3]);
}

// ---------------- fp16 weight transpose (4 weights): Wt[n,k] = W[k,n] --------
__global__ __launch_bounds__(256) void whalf_t(const float* __restrict__ W0,
                                               const float* __restrict__ W1,
                                               const float* __restrict__ W2,
                                               const float* __restrict__ W3,
                                               __half* __restrict__ outw) {
    __shared__ float t[32][33];
    const float* Ws[4] = {W0, W1, W2, W3};
    const float* W = Ws[blockIdx.z];
    __half* o = outw + (size_t)blockIdx.z * DIM * DIM;
    int k0 = blockIdx.x * 32, n0 = blockIdx.y * 32;
    int tx = threadIdx.x, ty = threadIdx.y;
#pragma unroll
    for (int j = 0; j < 4; j++)
        t[ty + 8 * j][tx] = W[(size_t)(k0 + ty + 8 * j) * DIM + n0 + tx];
    __syncthreads();
#pragma unroll
    for (int j = 0; j < 4; j++)
        o[(size_t)(n0 + ty + 8 * j) * DIM + k0 + tx] =
            __float2half_rn(t[tx][ty + 8 * j]);
}

// ---------------- fused q/k/v GEMM: single fp16 product ----------------
__global__ __launch_bounds__(256, 2) void gemm_qkv(
    const __half* __restrict__ A, const __half* __restrict__ Wf,
    const float* __restrict__ bq, const float* __restrict__ bk,
    const float* __restrict__ bv,
    __half* __restrict__ Qo, __half* __restrict__ Ko, __half* __restrict__ Vo) {
    extern __shared__ __half smq[];
    const int tid  = threadIdx.x;
    const int warp = tid >> 5, lane = tid & 31;
    const int g = lane >> 2, t4 = lane & 3;
    const int lr = lane & 7, sub = lane >> 3;
    const int wm = warp & 3, wn = warp >> 2;
    const int wsel = blockIdx.x >> 3;
    const int n0 = (blockIdx.x & 7) * 128;
    const int m0 = blockIdx.y * 128;
    const __half* B = Wf + (size_t)wsel * DIM * DIM;
    const float* bias = (wsel == 0) ? bq : ((wsel == 1) ? bk : bv);
    __half* C = (wsel == 0) ? Qo : ((wsel == 1) ? Ko : Vo);
    const float osc = (wsel == 0) ? 0.18033688011112042f : 1.0f;  // (1/8)*log2e

    auto load_chunk = [&](int kb, int st) {
        __half* sA = smq + st * 16384;
        __half* sB = sA + 8192;
#pragma unroll
        for (int i = 0; i < 4; i++) {
            int id = tid + i * 256;
            int r = id >> 3, cc = id & 7;
            int sidx = (r * 8 + ((cc ^ r) & 7)) * 8;
            cpasync16(sA + sidx, A + (size_t)(m0 + r) * DIM + kb * 64 + cc * 8);
            cpasync16(sB + sidx, B + (size_t)(n0 + r) * DIM + kb * 64 + cc * 8);
        }
    };

    float acc[2][8][4];
#pragma unroll
    for (int mt = 0; mt < 2; mt++)
#pragma unroll
        for (int nt = 0; nt < 8; nt++)
#pragma unroll
            for (int e = 0; e < 4; e++) acc[mt][nt][e] = 0.f;

    load_chunk(0, 0);
    cp_commit();

    const int NCH = DIM / 64;
    for (int kb = 0; kb < NCH; kb++) {
        int st = kb & 1;
        if (kb + 1 < NCH) { load_chunk(kb + 1, st ^ 1); cp_commit(); cp_wait<1>(); }
        else              { cp_wait<0>(); }
        __syncthreads();
        __half* sA = smq + st * 16384;
        __half* sB = sA + 8192;
#pragma unroll
        for (int kk = 0; kk < 4; kk++) {
            uint32_t af[2][4];
#pragma unroll
            for (int mt = 0; mt < 2; mt++)
                ldsm4(af[mt], saddr(sA + swzi64(wm * 32 + mt * 16 + lr + (sub & 1) * 8,
                                                kk * 16 + (sub >> 1) * 8)));
#pragma unroll
            for (int ntt = 0; ntt < 4; ntt++) {
                uint32_t bfg[4];
                ldsm4(bfg, saddr(sB + swzi64(wn * 64 + ntt * 16 + lr + (sub >> 1) * 8,
                                             kk * 16 + (sub & 1) * 8)));
#pragma unroll
                for (int mt = 0; mt < 2; mt++) {
                    mma_hf(acc[mt][2 * ntt],     af[mt], bfg[0], bfg[1]);
                    mma_hf(acc[mt][2 * ntt + 1], af[mt], bfg[2], bfg[3]);
                }
            }
        }
        __syncthreads();
    }

#pragma unroll
    for (int mt = 0; mt < 2; mt++) {
#pragma unroll
        for (int nt = 0; nt < 8; nt++) {
            int row0 = m0 + wm * 32 + mt * 16 + g;
            int col  = n0 + wn * 64 + nt * 8 + t4 * 2;
            float b0 = bias[col], b1 = bias[col + 1];
            *reinterpret_cast<__half2*>(C + (size_t)row0 * DIM + col) =
                __floats2half2_rn((acc[mt][nt][0] + b0) * osc,
                                  (acc[mt][nt][1] + b1) * osc);
            *reinterpret_cast<__half2*>(C + (size_t)(row0 + 8) * DIM + col) =
                __floats2half2_rn((acc[mt][nt][2] + b0) * osc,
                                  (acc[mt][nt][3] + b1) * osc);
        }
    }
}

// ---------------- out-proj GEMM: single fp16 product, fp32 out ----------------
__global__ __launch_bounds__(256, 2) void gemm_out(
    const __half* __restrict__ A, const __half* __restrict__ B,
    const float* __restrict__ bias, float* __restrict__ Cf) {
    extern __shared__ __half smq[];
    const int tid  = threadIdx.x;
    const int warp = tid >> 5, lane = tid & 31;
    const int g = lane >> 2, t4 = lane & 3;
    const int lr = lane & 7, sub = lane >> 3;
    const int wm = warp & 3, wn = warp >> 2;
    const int m0 = blockIdx.y * 128, n0 = blockIdx.x * 128;

    auto load_chunk = [&](int kb, int st) {
        __half* sA = smq + st * 16384;
        __half* sB = sA + 8192;
#pragma unroll
        for (int i = 0; i < 4; i++) {
            int id = tid + i * 256;
            int r = id >> 3, cc = id & 7;
            int sidx = (r * 8 + ((cc ^ r) & 7)) * 8;
            cpasync16(sA + sidx, A + (size_t)(m0 + r) * DIM + kb * 64 + cc * 8);
            cpasync16(sB + sidx, B + (size_t)(n0 + r) * DIM + kb * 64 + cc * 8);
        }
    };

    float acc[2][8][4];
#pragma unroll
    for (int mt = 0; mt < 2; mt++)
#pragma unroll
        for (int nt = 0; nt < 8; nt++)
#pragma unroll
            for (int e = 0; e < 4; e++) acc[mt][nt][e] = 0.f;

    load_chunk(0, 0);
    cp_commit();

    const int NCH = DIM / 64;
    for (int kb = 0; kb < NCH; kb++) {
        int st = kb & 1;
        if (kb + 1 < NCH) { load_chunk(kb + 1, st ^ 1); cp_commit(); cp_wait<1>(); }
        else              { cp_wait<0>(); }
        __syncthreads();
        __half* sA = smq + st * 16384;
        __half* sB = sA + 8192;
#pragma unroll
        for (int kk = 0; kk < 4; kk++) {
            uint32_t af[2][4];
#pragma unroll
            for (int mt = 0; mt < 2; mt++)
                ldsm4(af[mt], saddr(sA + swzi64(wm * 32 + mt * 16 + lr + (sub & 1) * 8,
                                                kk * 16 + (sub >> 1) * 8)));
#pragma unroll
            for (int ntt = 0; ntt < 4; ntt++) {
                uint32_t bfg[4];
                ldsm4(bfg, saddr(sB + swzi64(wn * 64 + ntt * 16 + lr + (sub >> 1) * 8,
                                             kk * 16 + (sub & 1) * 8)));
#pragma unroll
                for (int mt = 0; mt < 2; mt++) {
                    mma_hf(acc[mt][2 * ntt],     af[mt], bfg[0], bfg[1]);
                    mma_hf(acc[mt][2 * ntt + 1], af[mt], bfg[2], bfg[3]);
                }
            }
        }
        __syncthreads();
    }

#pragma unroll
    for (int mt = 0; mt < 2; mt++) {
#pragma unroll
        for (int nt = 0; nt < 8; nt++) {
            int row0 = m0 + wm * 32 + mt * 16 + g;
            int col  = n0 + wn * 64 + nt * 8 + t4 * 2;
            float b0 = bias[col], b1 = bias[col + 1];
            *reinterpret_cast<float2*>(Cf + (size_t)row0 * DIM + col) =
                make_float2(acc[mt][nt][0] + b0, acc[mt][nt][1] + b1);
            *reinterpret_cast<float2*>(Cf + (size_t)(row0 + 8) * DIM + col) =
                make_float2(acc[mt][nt][2] + b0, acc[mt][nt][3] + b1);
        }
    }
}

// ---------------- flash attention: 4 warps x 32 q-rows, Q in registers -------
// Q fragments hoisted out of the tile loop (loop-invariant): -8 ldsm/tile.
// smem (halfs): Q[0..8191] | K st{0,1} @8192+st*4096 | V st{0,1} @16384+st*4096
__global__ __launch_bounds__(128, 2) void flash_hf(
    const __half* __restrict__ Qf,
    const __half* __restrict__ Kf,
    const __half* __restrict__ Vf,
    __half* __restrict__ Of) {
    extern __shared__ __half smh[];
    __half* sQ = smh;                    // 128 x 64

    const int tid  = threadIdx.x;
    const int warp = tid >> 5, lane = tid & 31;
    const int g = lane >> 2, t4 = lane & 3;
    const int lr = lane & 7, sub = lane >> 3;
    const int head  = blockIdx.y;
    const int qt    = blockIdx.x;

    {
        const __half* qb = Qf + (size_t)(qt * 128) * DIM + head * DHEAD;
#pragma unroll
        for (int i = 0; i < 8; i++) {
            int id = tid + i * 128;
            int r = id >> 3, cc = id & 7;
            cpasync16(sQ + (r * 64 + ((cc ^ r) & 7) * 8),
                      qb + (size_t)r * DIM + cc * 8);
        }
    }
    auto load_kv = [&](int t, int st) {
        __half* sK = smh + 8192  + st * 4096;
        __half* sV = smh + 16384 + st * 4096;
        const size_t base = (size_t)(t * 64) * DIM + head * DHEAD;
#pragma unroll
        for (int i = 0; i < 4; i++) {
            int id = tid + i * 128;          // 0..511
            int r = id >> 3, cc = id & 7;
            int sidx = (r * 8 + ((cc ^ r) & 7)) * 8;
            cpasync16(sK + sidx, Kf + base + (size_t)r * DIM + cc * 8);
            cpasync16(sV + sidx, Vf + base + (size_t)r * DIM + cc * 8);
        }
    };

    float m_i[2][2], l_i[2][2], o[2][8][4];
#pragma unroll
    for (int mt = 0; mt < 2; mt++) {
        m_i[mt][0] = m_i[mt][1] = -1e30f;
        l_i[mt][0] = l_i[mt][1] = 0.f;
#pragma unroll
        for (int nt = 0; nt < 8; nt++)
#pragma unroll
            for (int e = 0; e < 4; e++) o[mt][nt][e] = 0.f;
    }

    const int NT = SEQ / 64;

    // prologue: Q + KV0 in group 0; drain, then hoist Q fragments to registers
    load_kv(0, 0);
    cp_commit();
    cp_wait<0>();
    __syncthreads();
    uint32_t qreg[2][4][4];
#pragma unroll
    for (int kk = 0; kk < 4; kk++)
#pragma unroll
        for (int mt = 0; mt < 2; mt++)
            ldsm4(qreg[mt][kk],
                  saddr(sQ + swzi64(warp * 32 + mt * 16 + lr + (sub & 1) * 8,
                                    kk * 16 + (sub >> 1) * 8)));

    for (int t = 0; t < NT; t++) {
        int st = t & 1;
        if (t + 1 < NT) { load_kv(t + 1, st ^ 1); cp_commit(); cp_wait<1>(); }
        else            { cp_wait<0>(); }
        __syncthreads();
        __half* sK = smh + 8192  + st * 4096;
        __half* sV = smh + 16384 + st * 4096;

        // ---- S = Q * K^T; Q from registers, K shared by 2 m-tiles ----
        float s[2][8][4];
#pragma unroll
        for (int mt = 0; mt < 2; mt++)
#pragma unroll
            for (int nt = 0; nt < 8; nt++)
#pragma unroll
                for (int e = 0; e < 4; e++) s[mt][nt][e] = 0.f;
#pragma unroll
        for (int kk = 0; kk < 4; kk++) {
#pragma unroll
            for (int ntt = 0; ntt < 4; ntt++) {
                uint32_t kf[4];
                ldsm4(kf, saddr(sK + swzi64(ntt * 16 + lr + (sub >> 1) * 8,
                                            kk * 16 + (sub & 1) * 8)));
#pragma unroll
                for (int mt = 0; mt < 2; mt++) {
                    mma_hf(s[mt][2 * ntt],     qreg[mt][kk], kf[0], kf[1]);
                    mma_hf(s[mt][2 * ntt + 1], qreg[mt][kk], kf[2], kf[3]);
                }
            }
        }

        // ---- lazy-rescale softmax (log2 domain) ----
        float tmx[2][2];
        bool need = false;
#pragma unroll
        for (int mt = 0; mt < 2; mt++)
#pragma unroll
            for (int r = 0; r < 2; r++) {
                float m = -1e30f;
#pragma unroll
                for (int j = 0; j < 8; j++)
                    m = fmaxf(m, fmaxf(s[mt][j][2 * r], s[mt][j][2 * r + 1]));
                tmx[mt][r] = m;
                need = need || (m > m_i[mt][r] + 8.f);
            }
        if (__any_sync(0xffffffffu, need)) {        // rare after early tiles
#pragma unroll
            for (int mt = 0; mt < 2; mt++)
#pragma unroll
                for (int r = 0; r < 2; r++) {
                    float m = fmaxf(tmx[mt][r], m_i[mt][r]);
                    m = fmaxf(m, __shfl_xor_sync(0xffffffffu, m, 1));
                    m = fmaxf(m, __shfl_xor_sync(0xffffffffu, m, 2));
                    float corr = ex2f(m_i[mt][r] - m);
                    m_i[mt][r] = m;
                    l_i[mt][r] *= corr;
#pragma unroll
                    for (int nt = 0; nt < 8; nt++) {
                        o[mt][nt][2 * r]     *= corr;
                        o[mt][nt][2 * r + 1] *= corr;
                    }
                }
        }
        // P against stable m_i (p <= 2^8; fp16 relative precision unchanged)
        uint32_t pa[2][8][2];
#pragma unroll
        for (int mt = 0; mt < 2; mt++) {
            __half2 ll0 = __floats2half2_rn(0.f, 0.f);
            __half2 ll1 = ll0;
#pragma unroll
            for (int j = 0; j < 8; j++) {
                pa[mt][j][0] = ex2h2(pack2h(s[mt][j][0] - m_i[mt][0],
                                            s[mt][j][1] - m_i[mt][0]));
                pa[mt][j][1] = ex2h2(pack2h(s[mt][j][2] - m_i[mt][1],
                                            s[mt][j][3] - m_i[mt][1]));
                ll0 = __hadd2(ll0, *reinterpret_cast<__half2*>(&pa[mt][j][0]));
                ll1 = __hadd2(ll1, *reinterpret_cast<__half2*>(&pa[mt][j][1]));
            }
            l_i[mt][0] += __low2float(ll0) + __high2float(ll0);
            l_i[mt][1] += __low2float(ll1) + __high2float(ll1);
        }

        // ---- O += P * V; V fragments shared by 2 m-tiles ----
#pragma unroll
        for (int kk = 0; kk < 4; kk++) {
            int j0 = 2 * kk, j1 = j0 + 1;
            uint32_t aH[2][4];
#pragma unroll
            for (int mt = 0; mt < 2; mt++) {
                aH[mt][0] = pa[mt][j0][0]; aH[mt][1] = pa[mt][j0][1];
                aH[mt][2] = pa[mt][j1][0]; aH[mt][3] = pa[mt][j1][1];
            }
#pragma unroll
            for (int ntt = 0; ntt < 4; ntt++) {
                uint32_t vf[4];
                ldsm4t(vf, saddr(sV + swzi64(kk * 16 + lr + (sub & 1) * 8,
                                             ntt * 16 + (sub >> 1) * 8)));
#pragma unroll
                for (int mt = 0; mt < 2; mt++) {
                    mma_hf(o[mt][2 * ntt],     aH[mt], vf[0], vf[1]);
                    mma_hf(o[mt][2 * ntt + 1], aH[mt], vf[2], vf[3]);
                }
            }
        }
        __syncthreads();
    }

    // final l reduction across the 4 lanes sharing each row, then store
#pragma unroll
    for (int mt = 0; mt < 2; mt++) {
#pragma unroll
        for (int r = 0; r < 2; r++) {
            l_i[mt][r] += __shfl_xor_sync(0xffffffffu, l_i[mt][r], 1);
            l_i[mt][r] += __shfl_xor_sync(0xffffffffu, l_i[mt][r], 2);
        }
        float inv0 = 1.f / l_i[mt][0], inv1 = 1.f / l_i[mt][1];
#pragma unroll
        for (int nt = 0; nt < 8; nt++) {
            int row0 = qt * 128 + warp * 32 + mt * 16 + g;
            int col  = head * DHEAD + nt * 8 + t4 * 2;
            *reinterpret_cast<__half2*>(Of + (size_t)row0 * DIM + col) =
                __floats2half2_rn(o[mt][nt][0] * inv0, o[mt][nt][1] * inv0);
            *reinterpret_cast<__half2*>(Of + (size_t)(row0 + 8) * DIM + col) =
                __floats2half2_rn(o[mt][nt][2] * inv1, o[mt][nt][3] * inv1);
        }
    }
}

// ---------------- residual + layernorm ----------------
__global__ __launch_bounds__(256) void ln_kernel(const float* __restrict__ h,
                                                 const float* __restrict__ pr,
                                                 const float* __restrict__ gamma,
                                                 const float* __restrict__ beta,
                                                 float* __restrict__ out) {
    __shared__ float red[16];
    __shared__ float s_mu, s_rstd;
    int row = blockIdx.x, tid = threadIdx.x;
    int c0 = tid * 4;
    float4 hv = *reinterpret_cast<const float4*>(h  + (size_t)row * DIM + c0);
    float4 pv = *reinterpret_cast<const float4*>(pr + (size_t)row * DIM + c0);
    float y[4] = {hv.x + pv.x, hv.y + pv.y, hv.z + pv.z, hv.w + pv.w};
    float sum = y[0] + y[1] + y[2] + y[3];
    float sq  = y[0]*y[0] + y[1]*y[1] + y[2]*y[2] + y[3]*y[3];
#pragma unroll
    for (int off = 16; off; off >>= 1) {
        sum += __shfl_xor_sync(0xffffffffu, sum, off);
        sq  += __shfl_xor_sync(0xffffffffu, sq,  off);
    }
    int w = tid >> 5;
    if ((tid & 31) == 0) { red[w] = sum; red[8 + w] = sq; }
    __syncthreads();
    if (tid == 0) {
        float ts = 0.f, tq = 0.f;
        for (int i = 0; i < 8; i++) { ts += red[i]; tq += red[8 + i]; }
        float mu = ts / (float)DIM;
        s_mu   = mu;
        s_rstd = rsqrtf(tq / (float)DIM - mu * mu + 1e-5f);
    }
    __syncthreads();
    float4 gv = *reinterpret_cast<const float4*>(gamma + c0);
    float4 bv = *reinterpret_cast<const float4*>(beta  + c0);
    float mu = s_mu, rs = s_rstd;
    float4 ov;
    ov.x = (y[0] - mu) * rs * gv.x + bv.x;
    ov.y = (y[1] - mu) * rs * gv.y + bv.y;
    ov.z = (y[2] - mu) * rs * gv.z + bv.z;
    ov.w = (y[3] - mu) * rs * gv.w + bv.w;
    *reinterpret_cast<float4*>(out + (size_t)row * DIM + c0) = ov;
}

// ---------------------------------------------------------------------------
extern "C" void kernel_launch(void* const* d_in, const int* in_sizes, int n_in,
                              void* d_out, int out_size) {
    (void)in_sizes; (void)n_in; (void)out_size;
    const float* x     = (const float*)d_in[0];
    const float* Wq    = (const float*)d_in[1];
    const float* bq    = (const float*)d_in[2];
    const float* Wk    = (const float*)d_in[3];
    const float* bk    = (const float*)d_in[4];
    const float* Wv    = (const float*)d_in[5];
    const float* bv    = (const float*)d_in[6];
    const float* Wo    = (const float*)d_in[7];
    const float* bo    = (const float*)d_in[8];
    const float* gamma = (const float*)d_in[9];
    const float* beta  = (const float*)d_in[10];
    float* out = (float*)d_out;

    void* p;
    cudaGetSymbolAddress(&p, g_h);    float* h    = (float*)p;
    cudaGetSymbolAddress(&p, g_proj); float* proj = (float*)p;
    cudaGetSymbolAddress(&p, g_hf);   __half* hf = (__half*)p;
    cudaGetSymbolAddress(&p, g_wf);   __half* wf = (__half*)p;
    cudaGetSymbolAddress(&p, g_qf);   __half* qf = (__half*)p;
    cudaGetSymbolAddress(&p, g_kf);   __half* kf = (__half*)p;
    cudaGetSymbolAddress(&p, g_vf);   __half* vf = (__half*)p;
    cudaGetSymbolAddress(&p, g_aof);  __half* aof = (__half*)p;

    const int SMEM_G = 65536;            // 2 stages x 32KB
    const int SMEM_F = 49152;            // Q 16KB + (K+V) x 2 stages x 8KB
    cudaFuncSetAttribute(gemm_qkv,
                         cudaFuncAttributeMaxDynamicSharedMemorySize, SMEM_G);
    cudaFuncSetAttribute(gemm_out,
                         cudaFuncAttributeMaxDynamicSharedMemorySize, SMEM_G);
    cudaFuncSetAttribute(flash_hf,
                         cudaFuncAttributeMaxDynamicSharedMemorySize, SMEM_F);

    add_pe<<<SEQ, 256>>>(x, h, hf);
    whalf_t<<<dim3(DIM / 32, DIM / 32, 4), dim3(32, 8)>>>(Wq, Wk, Wv, Wo, wf);

    gemm_qkv<<<dim3(24, SEQ / 128), 256, SMEM_G>>>(hf, wf, bq, bk, bv,
                                                   qf, kf, vf);

    flash_hf<<<dim3(SEQ / 128, NHEAD), 128, SMEM_F>>>(qf, kf, vf, aof);

    gemm_out<<<dim3(DIM / 128, SEQ / 128), 256, SMEM_G>>>(
        aof, wf + 3 * (size_t)DIM * DIM, bo, proj);

    ln_kernel<<<SEQ, 256>>>(h, proj, gamma, beta, out);
}

// round 16
// speedup vs baseline: 1.1351x; 1.0179x over previous
#include <cuda_runtime.h>
#include <cuda_bf16.h>
#include <cuda_fp16.h>
#include <math.h>
#include <stdint.h>

#define SEQ   4096
#define DIM   1024
#define NHEAD 16
#define DHEAD 64

// ---------------- scratch (no cudaMalloc allowed) ----------------
__device__ float  g_h   [SEQ*DIM];     // x + pe (fp32, residual)
__device__ float  g_proj[SEQ*DIM];     // final projection out (fp32)
__device__ __half g_hf[SEQ*DIM];       // x + pe (fp16, qkv GEMM input)
__device__ __half g_wf[4][DIM*DIM];    // Wq/Wk/Wv/Wo fp16, TRANSPOSED [N,K]
__device__ __half g_qf[SEQ*DIM], g_kf[SEQ*DIM], g_vf[SEQ*DIM];
__device__ __half g_aof[SEQ*DIM];      // attention out (fp16)

// ---------------- helpers ----------------
__device__ __forceinline__ uint32_t saddr(const void* p) {
    return (uint32_t)__cvta_generic_to_shared(p);
}
__device__ __forceinline__ float ex2f(float x) {
    float y; asm("ex2.approx.f32 %0, %1;" : "=f"(y) : "f"(x)); return y;
}
__device__ __forceinline__ uint32_t ex2h2(uint32_t x) {
    uint32_t y; asm("ex2.approx.f16x2 %0, %1;" : "=r"(y) : "r"(x)); return y;
}
__device__ __forceinline__ int swzi64(int row, int col) {
    return row * 64 + ((((col >> 3) ^ row) & 7) << 3);
}
__device__ __forceinline__ void ldsm4(uint32_t* r, uint32_t a) {
    asm volatile("ldmatrix.sync.aligned.m8n8.x4.shared.b16 {%0,%1,%2,%3},[%4];"
                 : "=r"(r[0]), "=r"(r[1]), "=r"(r[2]), "=r"(r[3]) : "r"(a));
}
__device__ __forceinline__ void ldsm4t(uint32_t* r, uint32_t a) {
    asm volatile("ldmatrix.sync.aligned.m8n8.x4.trans.shared.b16 {%0,%1,%2,%3},[%4];"
                 : "=r"(r[0]), "=r"(r[1]), "=r"(r[2]), "=r"(r[3]) : "r"(a));
}
__device__ __forceinline__ void mma_hf(float* c, const uint32_t* a,
                                       uint32_t b0, uint32_t b1) {
    asm volatile(
        "mma.sync.aligned.m16n8k16.row.col.f32.f16.f16.f32 "
        "{%0,%1,%2,%3},{%4,%5,%6,%7},{%8,%9},{%0,%1,%2,%3};"
        : "+f"(c[0]), "+f"(c[1]), "+f"(c[2]), "+f"(c[3])
        : "r"(a[0]), "r"(a[1]), "r"(a[2]), "r"(a[3]), "r"(b0), "r"(b1));
}
__device__ __forceinline__ uint32_t pack2h(float a, float b) {
    __half2 t = __floats2half2_rn(a, b);
    return *reinterpret_cast<uint32_t*>(&t);
}
__device__ __forceinline__ void cpasync16(void* dst, const void* src) {
    asm volatile("cp.async.cg.shared.global [%0], [%1], 16;"
                 :: "r"(saddr(dst)), "l"(src));
}
__device__ __forceinline__ void cp_commit() {
    asm volatile("cp.async.commit_group;" ::: "memory");
}
template <int N> __device__ __forceinline__ void cp_wait() {
    asm volatile("cp.async.wait_group %0;" :: "n"(N) : "memory");
}

// ---------------- h = x + pe (fp32 + fp16) ----------------
__global__ __launch_bounds__(256) void add_pe(const float* __restrict__ x,
                                              float* __restrict__ h,
                                              __half* __restrict__ hf) {
    int row = blockIdx.x;
    int c0  = threadIdx.x * 4;
    const float kf = -9.210340371976184f / (float)DIM;
    float4 xv = *reinterpret_cast<const float4*>(x + (size_t)row * DIM + c0);
    float v[4] = {xv.x, xv.y, xv.z, xv.w};
    float o[4];
#pragma unroll
    for (int e = 0; e < 4; e++) {
        int c = c0 + e;
        float div = expf((float)(c & ~1) * kf);
        float arg = (float)row * div;
        o[e] = v[e] + ((c & 1) ? cosf(arg) : sinf(arg));
    }
    size_t base = (size_t)row * DIM + c0;
    *reinterpret_cast<float4*>(h + base) = make_float4(o[0], o[1], o[2], o[3]);
    *reinterpret_cast<__half2*>(hf + base)     = __floats2half2_rn(o[0], o[1]);
    *reinterpret_cast<__half2*>(hf + base + 2) = __floats2half2_rn(o[2], o[3]);
}

// ---------------- fp16 weight transpose (4 weights): Wt[n,k] = W[k,n] --------
__global__ __launch_bounds__(256) void whalf_t(const float* __restrict__ W0,
                                               const float* __restrict__ W1,
                                               const float* __restrict__ W2,
                                               const float* __restrict__ W3,
                                               __half* __restrict__ outw) {
    __shared__ float t[32][33];
    const float* Ws[4] = {W0, W1, W2, W3};
    const float* W = Ws[blockIdx.z];
    __half* o = outw + (size_t)blockIdx.z * DIM * DIM;
    int k0 = blockIdx.x * 32, n0 = blockIdx.y * 32;
    int tx = threadIdx.x, ty = threadIdx.y;
#pragma unroll
    for (int j = 0; j < 4; j++)
        t[ty + 8 * j][tx] = W[(size_t)(k0 + ty + 8 * j) * DIM + n0 + tx];
    __syncthreads();
#pragma unroll
    for (int j = 0; j < 4; j++)
        o[(size_t)(n0 + ty + 8 * j) * DIM + k0 + tx] =
            __float2half_rn(t[tx][ty + 8 * j]);
}

// ---------------- fused q/k/v GEMM: single fp16 product ----------------
__global__ __launch_bounds__(256, 2) void gemm_qkv(
    const __half* __restrict__ A, const __half* __restrict__ Wf,
    const float* __restrict__ bq, const float* __restrict__ bk,
    const float* __restrict__ bv,
    __half* __restrict__ Qo, __half* __restrict__ Ko, __half* __restrict__ Vo) {
    extern __shared__ __half smq[];
    const int tid  = threadIdx.x;
    const int warp = tid >> 5, lane = tid & 31;
    const int g = lane >> 2, t4 = lane & 3;
    const int lr = lane & 7, sub = lane >> 3;
    const int wm = warp & 3, wn = warp >> 2;
    const int wsel = blockIdx.x >> 3;
    const int n0 = (blockIdx.x & 7) * 128;
    const int m0 = blockIdx.y * 128;
    const __half* B = Wf + (size_t)wsel * DIM * DIM;
    const float* bias = (wsel == 0) ? bq : ((wsel == 1) ? bk : bv);
    __half* C = (wsel == 0) ? Qo : ((wsel == 1) ? Ko : Vo);
    const float osc = (wsel == 0) ? 0.18033688011112042f : 1.0f;  // (1/8)*log2e

    auto load_chunk = [&](int kb, int st) {
        __half* sA = smq + st * 16384;
        __half* sB = sA + 8192;
#pragma unroll
        for (int i = 0; i < 4; i++) {
            int id = tid + i * 256;
            int r = id >> 3, cc = id & 7;
            int sidx = (r * 8 + ((cc ^ r) & 7)) * 8;
            cpasync16(sA + sidx, A + (size_t)(m0 + r) * DIM + kb * 64 + cc * 8);
            cpasync16(sB + sidx, B + (size_t)(n0 + r) * DIM + kb * 64 + cc * 8);
        }
    };

    float acc[2][8][4];
#pragma unroll
    for (int mt = 0; mt < 2; mt++)
#pragma unroll
        for (int nt = 0; nt < 8; nt++)
#pragma unroll
            for (int e = 0; e < 4; e++) acc[mt][nt][e] = 0.f;

    load_chunk(0, 0);
    cp_commit();

    const int NCH = DIM / 64;
    for (int kb = 0; kb < NCH; kb++) {
        int st = kb & 1;
        if (kb + 1 < NCH) { load_chunk(kb + 1, st ^ 1); cp_commit(); cp_wait<1>(); }
        else              { cp_wait<0>(); }
        __syncthreads();
        __half* sA = smq + st * 16384;
        __half* sB = sA + 8192;
#pragma unroll
        for (int kk = 0; kk < 4; kk++) {
            uint32_t af[2][4];
#pragma unroll
            for (int mt = 0; mt < 2; mt++)
                ldsm4(af[mt], saddr(sA + swzi64(wm * 32 + mt * 16 + lr + (sub & 1) * 8,
                                                kk * 16 + (sub >> 1) * 8)));
#pragma unroll
            for (int ntt = 0; ntt < 4; ntt++) {
                uint32_t bfg[4];
                ldsm4(bfg, saddr(sB + swzi64(wn * 64 + ntt * 16 + lr + (sub >> 1) * 8,
                                             kk * 16 + (sub & 1) * 8)));
#pragma unroll
                for (int mt = 0; mt < 2; mt++) {
                    mma_hf(acc[mt][2 * ntt],     af[mt], bfg[0], bfg[1]);
                    mma_hf(acc[mt][2 * ntt + 1], af[mt], bfg[2], bfg[3]);
                }
            }
        }
        __syncthreads();
    }

#pragma unroll
    for (int mt = 0; mt < 2; mt++) {
#pragma unroll
        for (int nt = 0; nt < 8; nt++) {
            int row0 = m0 + wm * 32 + mt * 16 + g;
            int col  = n0 + wn * 64 + nt * 8 + t4 * 2;
            float b0 = bias[col], b1 = bias[col + 1];
            *reinterpret_cast<__half2*>(C + (size_t)row0 * DIM + col) =
                __floats2half2_rn((acc[mt][nt][0] + b0) * osc,
                                  (acc[mt][nt][1] + b1) * osc);
            *reinterpret_cast<__half2*>(C + (size_t)(row0 + 8) * DIM + col) =
                __floats2half2_rn((acc[mt][nt][2] + b0) * osc,
                                  (acc[mt][nt][3] + b1) * osc);
        }
    }
}

// ---------------- out-proj GEMM: single fp16 product, fp32 out ----------------
__global__ __launch_bounds__(256, 2) void gemm_out(
    const __half* __restrict__ A, const __half* __restrict__ B,
    const float* __restrict__ bias, float* __restrict__ Cf) {
    extern __shared__ __half smq[];
    const int tid  = threadIdx.x;
    const int warp = tid >> 5, lane = tid & 31;
    const int g = lane >> 2, t4 = lane & 3;
    const int lr = lane & 7, sub = lane >> 3;
    const int wm = warp & 3, wn = warp >> 2;
    const int m0 = blockIdx.y * 128, n0 = blockIdx.x * 128;

    auto load_chunk = [&](int kb, int st) {
        __half* sA = smq + st * 16384;
        __half* sB = sA + 8192;
#pragma unroll
        for (int i = 0; i < 4; i++) {
            int id = tid + i * 256;
            int r = id >> 3, cc = id & 7;
            int sidx = (r * 8 + ((cc ^ r) & 7)) * 8;
            cpasync16(sA + sidx, A + (size_t)(m0 + r) * DIM + kb * 64 + cc * 8);
            cpasync16(sB + sidx, B + (size_t)(n0 + r) * DIM + kb * 64 + cc * 8);
        }
    };

    float acc[2][8][4];
#pragma unroll
    for (int mt = 0; mt < 2; mt++)
#pragma unroll
        for (int nt = 0; nt < 8; nt++)
#pragma unroll
            for (int e = 0; e < 4; e++) acc[mt][nt][e] = 0.f;

    load_chunk(0, 0);
    cp_commit();

    const int NCH = DIM / 64;
    for (int kb = 0; kb < NCH; kb++) {
        int st = kb & 1;
        if (kb + 1 < NCH) { load_chunk(kb + 1, st ^ 1); cp_commit(); cp_wait<1>(); }
        else              { cp_wait<0>(); }
        __syncthreads();
        __half* sA = smq + st * 16384;
        __half* sB = sA + 8192;
#pragma unroll
        for (int kk = 0; kk < 4; kk++) {
            uint32_t af[2][4];
#pragma unroll
            for (int mt = 0; mt < 2; mt++)
                ldsm4(af[mt], saddr(sA + swzi64(wm * 32 + mt * 16 + lr + (sub & 1) * 8,
                                                kk * 16 + (sub >> 1) * 8)));
#pragma unroll
            for (int ntt = 0; ntt < 4; ntt++) {
                uint32_t bfg[4];
                ldsm4(bfg, saddr(sB + swzi64(wn * 64 + ntt * 16 + lr + (sub >> 1) * 8,
                                             kk * 16 + (sub & 1) * 8)));
#pragma unroll
                for (int mt = 0; mt < 2; mt++) {
                    mma_hf(acc[mt][2 * ntt],     af[mt], bfg[0], bfg[1]);
                    mma_hf(acc[mt][2 * ntt + 1], af[mt], bfg[2], bfg[3]);
                }
            }
        }
        __syncthreads();
    }

#pragma unroll
    for (int mt = 0; mt < 2; mt++) {
#pragma unroll
        for (int nt = 0; nt < 8; nt++) {
            int row0 = m0 + wm * 32 + mt * 16 + g;
            int col  = n0 + wn * 64 + nt * 8 + t4 * 2;
            float b0 = bias[col], b1 = bias[col + 1];
            *reinterpret_cast<float2*>(Cf + (size_t)row0 * DIM + col) =
                make_float2(acc[mt][nt][0] + b0, acc[mt][nt][1] + b1);
            *reinterpret_cast<float2*>(Cf + (size_t)(row0 + 8) * DIM + col) =
                make_float2(acc[mt][nt][2] + b0, acc[mt][nt][3] + b1);
        }
    }
}

// ---------------- flash attention: relative-domain softmax -------------------
// S accumulators are initialized to -m_i, so the MMA emits max-relative scores
// directly (no per-element subtraction). m_i starts at 0 (raw domain). Rescale
// triggers only when a tile's relative max exceeds 8 (p <= 2^8 in fp16).
__global__ __launch_bounds__(128, 2) void flash_hf(
    const __half* __restrict__ Qf,
    const __half* __restrict__ Kf,
    const __half* __restrict__ Vf,
    __half* __restrict__ Of) {
    extern __shared__ __half smh[];
    __half* sQ = smh;                    // 128 x 64

    const int tid  = threadIdx.x;
    const int warp = tid >> 5, lane = tid & 31;
    const int g = lane >> 2, t4 = lane & 3;
    const int lr = lane & 7, sub = lane >> 3;
    const int head  = blockIdx.y;
    const int qt    = blockIdx.x;

    {
        const __half* qb = Qf + (size_t)(qt * 128) * DIM + head * DHEAD;
#pragma unroll
        for (int i = 0; i < 8; i++) {
            int id = tid + i * 128;
            int r = id >> 3, cc = id & 7;
            cpasync16(sQ + (r * 64 + ((cc ^ r) & 7) * 8),
                      qb + (size_t)r * DIM + cc * 8);
        }
    }
    auto load_kv = [&](int t, int st) {
        __half* sK = smh + 8192  + st * 4096;
        __half* sV = smh + 16384 + st * 4096;
        const size_t base = (size_t)(t * 64) * DIM + head * DHEAD;
#pragma unroll
        for (int i = 0; i < 4; i++) {
            int id = tid + i * 128;          // 0..511
            int r = id >> 3, cc = id & 7;
            int sidx = (r * 8 + ((cc ^ r) & 7)) * 8;
            cpasync16(sK + sidx, Kf + base + (size_t)r * DIM + cc * 8);
            cpasync16(sV + sidx, Vf + base + (size_t)r * DIM + cc * 8);
        }
    };

    float m_i[2][2], l_i[2][2], o[2][8][4];
#pragma unroll
    for (int mt = 0; mt < 2; mt++) {
        m_i[mt][0] = m_i[mt][1] = 0.f;       // raw-score domain reference
        l_i[mt][0] = l_i[mt][1] = 0.f;
#pragma unroll
        for (int nt = 0; nt < 8; nt++)
#pragma unroll
            for (int e = 0; e < 4; e++) o[mt][nt][e] = 0.f;
    }

    const int NT = SEQ / 64;

    // prologue: Q + KV0 in group 0; drain, then hoist Q fragments to registers
    load_kv(0, 0);
    cp_commit();
    cp_wait<0>();
    __syncthreads();
    uint32_t qreg[2][4][4];
#pragma unroll
    for (int kk = 0; kk < 4; kk++)
#pragma unroll
        for (int mt = 0; mt < 2; mt++)
            ldsm4(qreg[mt][kk],
                  saddr(sQ + swzi64(warp * 32 + mt * 16 + lr + (sub & 1) * 8,
                                    kk * 16 + (sub >> 1) * 8)));

    for (int t = 0; t < NT; t++) {
        int st = t & 1;
        if (t + 1 < NT) { load_kv(t + 1, st ^ 1); cp_commit(); cp_wait<1>(); }
        else            { cp_wait<0>(); }
        __syncthreads();
        __half* sK = smh + 8192  + st * 4096;
        __half* sV = smh + 16384 + st * 4096;

        // ---- S = Q*K^T - m_i (subtraction folded into accumulator init) ----
        float s[2][8][4];
#pragma unroll
        for (int mt = 0; mt < 2; mt++) {
            float i0 = -m_i[mt][0], i1 = -m_i[mt][1];
#pragma unroll
            for (int nt = 0; nt < 8; nt++) {
                s[mt][nt][0] = i0; s[mt][nt][1] = i0;
                s[mt][nt][2] = i1; s[mt][nt][3] = i1;
            }
        }
#pragma unroll
        for (int kk = 0; kk < 4; kk++) {
#pragma unroll
            for (int ntt = 0; ntt < 4; ntt++) {
                uint32_t kf[4];
                ldsm4(kf, saddr(sK + swzi64(ntt * 16 + lr + (sub >> 1) * 8,
                                            kk * 16 + (sub & 1) * 8)));
#pragma unroll
                for (int mt = 0; mt < 2; mt++) {
                    mma_hf(s[mt][2 * ntt],     qreg[mt][kk], kf[0], kf[1]);
                    mma_hf(s[mt][2 * ntt + 1], qreg[mt][kk], kf[2], kf[3]);
                }
            }
        }

        // ---- lazy rescale: trigger when relative max exceeds 8 ----
        float mrel[2][2];
        bool need = false;
#pragma unroll
        for (int mt = 0; mt < 2; mt++)
#pragma unroll
            for (int r = 0; r < 2; r++) {
                float m = -1e30f;
#pragma unroll
                for (int j = 0; j < 8; j++)
                    m = fmaxf(m, fmaxf(s[mt][j][2 * r], s[mt][j][2 * r + 1]));
                mrel[mt][r] = m;
                need = need || (m > 8.f);
            }
        if (__any_sync(0xffffffffu, need)) {        // rare
#pragma unroll
            for (int mt = 0; mt < 2; mt++)
#pragma unroll
                for (int r = 0; r < 2; r++) {
                    float mm = fmaxf(mrel[mt][r], 0.f);
                    mm = fmaxf(mm, __shfl_xor_sync(0xffffffffu, mm, 1));
                    mm = fmaxf(mm, __shfl_xor_sync(0xffffffffu, mm, 2));
                    float corr = ex2f(-mm);
                    m_i[mt][r] += mm;
                    l_i[mt][r] *= corr;
#pragma unroll
                    for (int nt = 0; nt < 8; nt++) {
                        o[mt][nt][2 * r]     *= corr;
                        o[mt][nt][2 * r + 1] *= corr;
                        s[mt][nt][2 * r]     -= mm;
                        s[mt][nt][2 * r + 1] -= mm;
                    }
                }
        }
        // P = 2^s directly (s already max-relative; p <= 2^8 in fp16)
        uint32_t pa[2][8][2];
#pragma unroll
        for (int mt = 0; mt < 2; mt++) {
            __half2 ll0 = __floats2half2_rn(0.f, 0.f);
            __half2 ll1 = ll0;
#pragma unroll
            for (int j = 0; j < 8; j++) {
                pa[mt][j][0] = ex2h2(pack2h(s[mt][j][0], s[mt][j][1]));
                pa[mt][j][1] = ex2h2(pack2h(s[mt][j][2], s[mt][j][3]));
                ll0 = __hadd2(ll0, *reinterpret_cast<__half2*>(&pa[mt][j][0]));
                ll1 = __hadd2(ll1, *reinterpret_cast<__half2*>(&pa[mt][j][1]));
            }
            l_i[mt][0] += __low2float(ll0) + __high2float(ll0);
            l_i[mt][1] += __low2float(ll1) + __high2float(ll1);
        }

        // ---- O += P * V; V fragments shared by 2 m-tiles ----
#pragma unroll
        for (int kk = 0; kk < 4; kk++) {
            int j0 = 2 * kk, j1 = j0 + 1;
            uint32_t aH[2][4];
#pragma unroll
            for (int mt = 0; mt < 2; mt++) {
                aH[mt][0] = pa[mt][j0][0]; aH[mt][1] = pa[mt][j0][1];
                aH[mt][2] = pa[mt][j1][0]; aH[mt][3] = pa[mt][j1][1];
            }
#pragma unroll
            for (int ntt = 0; ntt < 4; ntt++) {
                uint32_t vf[4];
                ldsm4t(vf, saddr(sV + swzi64(kk * 16 + lr + (sub & 1) * 8,
                                             ntt * 16 + (sub >> 1) * 8)));
#pragma unroll
                for (int mt = 0; mt < 2; mt++) {
                    mma_hf(o[mt][2 * ntt],     aH[mt], vf[0], vf[1]);
                    mma_hf(o[mt][2 * ntt + 1], aH[mt], vf[2], vf[3]);
                }
            }
        }
        __syncthreads();
    }

    // final l reduction across the 4 lanes sharing each row, then store
#pragma unroll
    for (int mt = 0; mt < 2; mt++) {
#pragma unroll
        for (int r = 0; r < 2; r++) {
            l_i[mt][r] += __shfl_xor_sync(0xffffffffu, l_i[mt][r], 1);
            l_i[mt][r] += __shfl_xor_sync(0xffffffffu, l_i[mt][r], 2);
        }
        float inv0 = 1.f / l_i[mt][0], inv1 = 1.f / l_i[mt][1];
#pragma unroll
        for (int nt = 0; nt < 8; nt++) {
            int row0 = qt * 128 + warp * 32 + mt * 16 + g;
            int col  = head * DHEAD + nt * 8 + t4 * 2;
            *reinterpret_cast<__half2*>(Of + (size_t)row0 * DIM + col) =
                __floats2half2_rn(o[mt][nt][0] * inv0, o[mt][nt][1] * inv0);
            *reinterpret_cast<__half2*>(Of + (size_t)(row0 + 8) * DIM + col) =
                __floats2half2_rn(o[mt][nt][2] * inv1, o[mt][nt][3] * inv1);
        }
    }
}

// ---------------- residual + layernorm ----------------
__global__ __launch_bounds__(256) void ln_kernel(const float* __restrict__ h,
                                                 const float* __restrict__ pr,
                                                 const float* __restrict__ gamma,
                                                 const float* __restrict__ beta,
                                                 float* __restrict__ out) {
    __shared__ float red[16];
    __shared__ float s_mu, s_rstd;
    int row = blockIdx.x, tid = threadIdx.x;
    int c0 = tid * 4;
    float4 hv = *reinterpret_cast<const float4*>(h  + (size_t)row * DIM + c0);
    float4 pv = *reinterpret_cast<const float4*>(pr + (size_t)row * DIM + c0);
    float y[4] = {hv.x + pv.x, hv.y + pv.y, hv.z + pv.z, hv.w + pv.w};
    float sum = y[0] + y[1] + y[2] + y[3];
    float sq  = y[0]*y[0] + y[1]*y[1] + y[2]*y[2] + y[3]*y[3];
#pragma unroll
    for (int off = 16; off; off >>= 1) {
        sum += __shfl_xor_sync(0xffffffffu, sum, off);
        sq  += __shfl_xor_sync(0xffffffffu, sq,  off);
    }
    int w = tid >> 5;
    if ((tid & 31) == 0) { red[w] = sum; red[8 + w] = sq; }
    __syncthreads();
    if (tid == 0) {
        float ts = 0.f, tq = 0.f;
        for (int i = 0; i < 8; i++) { ts += red[i]; tq += red[8 + i]; }
        float mu = ts / (float)DIM;
        s_mu   = mu;
        s_rstd = rsqrtf(tq / (float)DIM - mu * mu + 1e-5f);
    }
    __syncthreads();
    float4 gv = *reinterpret_cast<const float4*>(gamma + c0);
    float4 bv = *reinterpret_cast<const float4*>(beta  + c0);
    float mu = s_mu, rs = s_rstd;
    float4 ov;
    ov.x = (y[0] - mu) * rs * gv.x + bv.x;
    ov.y = (y[1] - mu) * rs * gv.y + bv.y;
    ov.z = (y[2] - mu) * rs * gv.z + bv.z;
    ov.w = (y[3] - mu) * rs * gv.w + bv.w;
    *reinterpret_cast<float4*>(out + (size_t)row * DIM + c0) = ov;
}

// ---------------------------------------------------------------------------
extern "C" void kernel_launch(void* const* d_in, const int* in_sizes, int n_in,
                              void* d_out, int out_size) {
    (void)in_sizes; (void)n_in; (void)out_size;
    const float* x     = (const float*)d_in[0];
    const float* Wq    = (const float*)d_in[1];
    const float* bq    = (const float*)d_in[2];
    const float* Wk    = (const float*)d_in[3];
    const float* bk    = (const float*)d_in[4];
    const float* Wv    = (const float*)d_in[5];
    const float* bv    = (const float*)d_in[6];
    const float* Wo    = (const float*)d_in[7];
    const float* bo    = (const float*)d_in[8];
    const float* gamma = (const float*)d_in[9];
    const float* beta  = (const float*)d_in[10];
    float* out = (float*)d_out;

    void* p;
    cudaGetSymbolAddress(&p, g_h);    float* h    = (float*)p;
    cudaGetSymbolAddress(&p, g_proj); float* proj = (float*)p;
    cudaGetSymbolAddress(&p, g_hf);   __half* hf = (__half*)p;
    cudaGetSymbolAddress(&p, g_wf);   __half* wf = (__half*)p;
    cudaGetSymbolAddress(&p, g_qf);   __half* qf = (__half*)p;
    cudaGetSymbolAddress(&p, g_kf);   __half* kf = (__half*)p;
    cudaGetSymbolAddress(&p, g_vf);   __half* vf = (__half*)p;
    cudaGetSymbolAddress(&p, g_aof);  __half* aof = (__half*)p;

    const int SMEM_G = 65536;            // 2 stages x 32KB
    const int SMEM_F = 49152;            // Q 16KB + (K+V) x 2 stages x 8KB
    cudaFuncSetAttribute(gemm_qkv,
                         cudaFuncAttributeMaxDynamicSharedMemorySize, SMEM_G);
    cudaFuncSetAttribute(gemm_out,
                         cudaFuncAttributeMaxDynamicSharedMemorySize, SMEM_G);
    cudaFuncSetAttribute(flash_hf,
                         cudaFuncAttributeMaxDynamicSharedMemorySize, SMEM_F);

    add_pe<<<SEQ, 256>>>(x, h, hf);
    whalf_t<<<dim3(DIM / 32, DIM / 32, 4), dim3(32, 8)>>>(Wq, Wk, Wv, Wo, wf);

    gemm_qkv<<<dim3(24, SEQ / 128), 256, SMEM_G>>>(hf, wf, bq, bk, bv,
                                                   qf, kf, vf);

    flash_hf<<<dim3(SEQ / 128, NHEAD), 128, SMEM_F>>>(qf, kf, vf, aof);

    gemm_out<<<dim3(DIM / 128, SEQ / 128), 256, SMEM_G>>>(
        aof, wf + 3 * (size_t)DIM * DIM, bo, proj);

    ln_kernel<<<SEQ, 256>>>(h, proj, gamma, beta, out);
}